// round 2
// baseline (speedup 1.0000x reference)
#include <cuda_runtime.h>
#include <cuda_bf16.h>

#define NN 100000
#define EE 1600000
#define DD 128

// ---------------- scratch (static device arrays; no allocation) ----------------
__device__ float g_h[(size_t)NN * DD];     // GEMM output / aggregation input
__device__ float g_z[(size_t)NN * DD];     // aggregation output (layer activations)
__device__ int   g_count[NN];
__device__ int   g_rowptr[NN + 1];
__device__ int   g_cursor[NN];
__device__ float g_dinv[NN];
__device__ int   g_csrc[EE];
__device__ float g_cw[EE];

// ---------------- graph preprocessing ----------------
__global__ void zero_count_kernel(int n) {
    int i = blockIdx.x * blockDim.x + threadIdx.x;
    if (i < n) g_count[i] = 0;
}

__global__ void count_kernel(const int* __restrict__ ei, int E, int n) {
    int e = blockIdx.x * blockDim.x + threadIdx.x;
    if (e < E) {
        int d = ei[(size_t)E + e];
        if ((unsigned)d < (unsigned)n) atomicAdd(&g_count[d], 1);
    }
}

__global__ void dinv_kernel(int n) {
    int i = blockIdx.x * blockDim.x + threadIdx.x;
    if (i < n) g_dinv[i] = rsqrtf((float)g_count[i] + 1.0f);  // +1 self loop
}

// single-block exclusive scan over g_count -> g_rowptr (and g_cursor copy)
__global__ void scan_kernel(int n) {
    __shared__ int wsum[32];
    __shared__ int chunk_total;
    int t = threadIdx.x, lane = t & 31, wid = t >> 5;
    int carry = 0;
    for (int base = 0; base < n; base += 1024) {
        int idx = base + t;
        int v = (idx < n) ? g_count[idx] : 0;
        int x = v;
        #pragma unroll
        for (int off = 1; off < 32; off <<= 1) {
            int y = __shfl_up_sync(0xFFFFFFFFu, x, off);
            if (lane >= off) x += y;
        }
        if (lane == 31) wsum[wid] = x;
        __syncthreads();
        if (wid == 0) {
            int s = wsum[lane];
            #pragma unroll
            for (int off = 1; off < 32; off <<= 1) {
                int y = __shfl_up_sync(0xFFFFFFFFu, s, off);
                if (lane >= off) s += y;
            }
            wsum[lane] = s;
            if (lane == 31) chunk_total = s;
        }
        __syncthreads();
        int woff = (wid > 0) ? wsum[wid - 1] : 0;
        int excl = carry + woff + x - v;
        if (idx < n) { g_rowptr[idx] = excl; g_cursor[idx] = excl; }
        carry += chunk_total;
        __syncthreads();
    }
    if (t == 0) g_rowptr[n] = carry;
}

__global__ void fill_kernel(const int* __restrict__ ei, int E, int n) {
    int e = blockIdx.x * blockDim.x + threadIdx.x;
    if (e < E) {
        int s = ei[e];
        int d = ei[(size_t)E + e];
        if ((unsigned)s < (unsigned)n && (unsigned)d < (unsigned)n) {
            int p = atomicAdd(&g_cursor[d], 1);
            g_csrc[p] = s;
            g_cw[p] = g_dinv[s] * g_dinv[d];
        }
    }
}

// ---------------- GEMM: C[n x 128] = A[n x 128] @ W[128 x 128] ----------------
__global__ __launch_bounds__(256) void gemm128_kernel(
    const float* __restrict__ A, const float* __restrict__ W,
    float* __restrict__ C, int n)
{
    __shared__ float Xs[32][136];   // transposed [k][row], pitch 136 kills store conflicts
    __shared__ float Ws[32][128];   // [k][col]
    int block_row = blockIdx.x * 128;
    int t = threadIdx.x;
    int tx = t & 15, ty = t >> 4;   // 16x16 thread grid; 8x8 micro-tile

    float acc[8][8];
    #pragma unroll
    for (int i = 0; i < 8; i++)
        #pragma unroll
        for (int j = 0; j < 8; j++) acc[i][j] = 0.0f;

    for (int kb = 0; kb < 128; kb += 32) {
        // X tile: 128 rows x 32 k, transposed into Xs[k][row]
        int chunk = t & 7;      // float4 index within 32 k
        int rr = t >> 3;        // 0..31
        #pragma unroll
        for (int i = 0; i < 4; i++) {
            int r = rr + i * 32;
            int grow = block_row + r;
            float4 v = make_float4(0.f, 0.f, 0.f, 0.f);
            if (grow < n) v = *(const float4*)(A + (size_t)grow * 128 + kb + chunk * 4);
            Xs[chunk * 4 + 0][r] = v.x;
            Xs[chunk * 4 + 1][r] = v.y;
            Xs[chunk * 4 + 2][r] = v.z;
            Xs[chunk * 4 + 3][r] = v.w;
        }
        // W tile: 32 k x 128 cols
        #pragma unroll
        for (int i = 0; i < 4; i++) {
            int idx = t + i * 256;      // float4 index 0..1023
            int k = idx >> 5;
            int c = (idx & 31) << 2;
            *(float4*)&Ws[k][c] = *(const float4*)(W + (size_t)(kb + k) * 128 + c);
        }
        __syncthreads();

        #pragma unroll
        for (int k = 0; k < 32; k++) {
            float a[8], b[8];
            *(float4*)&a[0] = *(const float4*)&Xs[k][ty * 8];
            *(float4*)&a[4] = *(const float4*)&Xs[k][ty * 8 + 4];
            *(float4*)&b[0] = *(const float4*)&Ws[k][tx * 8];
            *(float4*)&b[4] = *(const float4*)&Ws[k][tx * 8 + 4];
            #pragma unroll
            for (int i = 0; i < 8; i++)
                #pragma unroll
                for (int j = 0; j < 8; j++)
                    acc[i][j] = fmaf(a[i], b[j], acc[i][j]);
        }
        __syncthreads();
    }

    #pragma unroll
    for (int i = 0; i < 8; i++) {
        int grow = block_row + ty * 8 + i;
        if (grow < n) {
            *(float4*)(C + (size_t)grow * 128 + tx * 8) =
                make_float4(acc[i][0], acc[i][1], acc[i][2], acc[i][3]);
            *(float4*)(C + (size_t)grow * 128 + tx * 8 + 4) =
                make_float4(acc[i][4], acc[i][5], acc[i][6], acc[i][7]);
        }
    }
}

// ---------------- aggregation: out[i] = relu(sum_{e in CSC(i)} h[src]*w + h[i]*dinv^2 + b) ----
__global__ __launch_bounds__(256) void aggregate_kernel(
    const float* __restrict__ h, const float* __restrict__ bias,
    float* __restrict__ out, int n)
{
    int warp = (blockIdx.x * blockDim.x + threadIdx.x) >> 5;
    int lane = threadIdx.x & 31;
    if (warp >= n) return;
    int i = warp;

    float di = g_dinv[i];
    float w0 = di * di;
    float4 v = ((const float4*)(h + (size_t)i * 128))[lane];
    float4 acc  = make_float4(v.x * w0, v.y * w0, v.z * w0, v.w * w0);
    float4 acc2 = make_float4(0.f, 0.f, 0.f, 0.f);

    int e0 = g_rowptr[i], e1 = g_rowptr[i + 1];
    int e = e0;
    for (; e + 1 < e1; e += 2) {
        int s0 = g_csrc[e];     float w_0 = g_cw[e];
        int s1 = g_csrc[e + 1]; float w_1 = g_cw[e + 1];
        float4 h0 = ((const float4*)(h + (size_t)s0 * 128))[lane];
        float4 h1 = ((const float4*)(h + (size_t)s1 * 128))[lane];
        acc.x  = fmaf(h0.x, w_0, acc.x);  acc.y  = fmaf(h0.y, w_0, acc.y);
        acc.z  = fmaf(h0.z, w_0, acc.z);  acc.w  = fmaf(h0.w, w_0, acc.w);
        acc2.x = fmaf(h1.x, w_1, acc2.x); acc2.y = fmaf(h1.y, w_1, acc2.y);
        acc2.z = fmaf(h1.z, w_1, acc2.z); acc2.w = fmaf(h1.w, w_1, acc2.w);
    }
    if (e < e1) {
        int s0 = g_csrc[e]; float w_0 = g_cw[e];
        float4 h0 = ((const float4*)(h + (size_t)s0 * 128))[lane];
        acc.x = fmaf(h0.x, w_0, acc.x); acc.y = fmaf(h0.y, w_0, acc.y);
        acc.z = fmaf(h0.z, w_0, acc.z); acc.w = fmaf(h0.w, w_0, acc.w);
    }
    acc.x += acc2.x; acc.y += acc2.y; acc.z += acc2.z; acc.w += acc2.w;

    float4 bb = ((const float4*)bias)[lane];
    acc.x = fmaxf(acc.x + bb.x, 0.0f);
    acc.y = fmaxf(acc.y + bb.y, 0.0f);
    acc.z = fmaxf(acc.z + bb.z, 0.0f);
    acc.w = fmaxf(acc.w + bb.w, 0.0f);
    ((float4*)(out + (size_t)i * 128))[lane] = acc;
}

// ---------------- decode: out[e] = dot(z[s], z[d]) ----------------
__global__ __launch_bounds__(256) void decode_kernel(
    const float* __restrict__ z, const int* __restrict__ eli,
    float* __restrict__ out, int el)
{
    int warp = (blockIdx.x * blockDim.x + threadIdx.x) >> 5;
    int lane = threadIdx.x & 31;
    if (warp >= el) return;
    int s = eli[warp];
    int d = eli[(size_t)el + warp];
    float4 a = ((const float4*)(z + (size_t)s * 128))[lane];
    float4 b = ((const float4*)(z + (size_t)d * 128))[lane];
    float p = a.x * b.x + a.y * b.y + a.z * b.z + a.w * b.w;
    #pragma unroll
    for (int off = 16; off; off >>= 1) p += __shfl_down_sync(0xFFFFFFFFu, p, off);
    if (lane == 0) out[warp] = p;
}

// ---------------- launch ----------------
extern "C" void kernel_launch(void* const* d_in, const int* in_sizes, int n_in,
                              void* d_out, int out_size)
{
    const float* x   = (const float*)d_in[0];
    const int*   ei  = (const int*)d_in[1];    // int64 tensors arrive as int32
    const int*   eli = (const int*)d_in[2];
    const float* W1  = (const float*)d_in[3];
    const float* b1  = (const float*)d_in[4];
    const float* W2  = (const float*)d_in[5];
    const float* b2  = (const float*)d_in[6];
    float* out = (float*)d_out;

    int n  = in_sizes[0] / DD;      // nodes
    int E  = in_sizes[1] / 2;       // edges
    int el = in_sizes[2] / 2;       // label edges

    float* h = nullptr; float* z = nullptr;
    cudaGetSymbolAddress((void**)&h, g_h);
    cudaGetSymbolAddress((void**)&z, g_z);

    const int T = 256;
    int nb_n = (n + T - 1) / T;
    int nb_e = (E + T - 1) / T;
    int nb_warpN = (n * 32 + T - 1) / T;   // one warp per node
    int nb_warpL = (el * 32 + T - 1) / T;  // one warp per label edge
    int nb_gemm = (n + 127) / 128;

    // graph preprocessing (shared by both layers)
    zero_count_kernel<<<nb_n, T>>>(n);
    count_kernel<<<nb_e, T>>>(ei, E, n);
    dinv_kernel<<<nb_n, T>>>(n);
    scan_kernel<<<1, 1024>>>(n);
    fill_kernel<<<nb_e, T>>>(ei, E, n);

    // layer 1: h = x@W1 ; z = relu(agg(h) + b1)
    gemm128_kernel<<<nb_gemm, T>>>(x, W1, h, n);
    aggregate_kernel<<<nb_warpN, T>>>(h, b1, z, n);

    // layer 2: h = z@W2 ; z = relu(agg(h) + b2)
    gemm128_kernel<<<nb_gemm, T>>>(z, W2, h, n);
    aggregate_kernel<<<nb_warpN, T>>>(h, b2, z, n);

    // decode
    decode_kernel<<<nb_warpL, T>>>(z, eli, out, el);
}

// round 3
// speedup vs baseline: 1.1430x; 1.1430x over previous
#include <cuda_runtime.h>
#include <cuda_bf16.h>

#define NN 100000
#define EE 1600000
#define DD 128
#define SCAN_BLK 1024

// ---------------- scratch (static device arrays; no allocation) ----------------
__device__ float g_h[(size_t)NN * DD];     // GEMM output / aggregation input
__device__ float g_z[(size_t)NN * DD];     // aggregation output (layer activations)
__device__ int   g_count[NN];
__device__ int   g_rowptr[NN + 1];
__device__ int   g_cursor[NN];
__device__ float g_dinv[NN];
__device__ int   g_csrc[EE];
__device__ float g_cw[EE];
__device__ int   g_blocksum[1024];
__device__ int   g_blockoff[1025];

// ---------------- graph preprocessing ----------------
__global__ void zero_count_kernel(int n) {
    int i = blockIdx.x * blockDim.x + threadIdx.x;
    if (i < n) g_count[i] = 0;
}

__global__ void count_kernel(const int* __restrict__ ei, int E, int n) {
    int e = blockIdx.x * blockDim.x + threadIdx.x;
    if (e < E) {
        int d = ei[(size_t)E + e];
        if ((unsigned)d < (unsigned)n) atomicAdd(&g_count[d], 1);
    }
}

__global__ void dinv_kernel(int n) {
    int i = blockIdx.x * blockDim.x + threadIdx.x;
    if (i < n) g_dinv[i] = rsqrtf((float)g_count[i] + 1.0f);  // +1 self loop
}

// block-level inclusive scan helper (1024 threads)
__device__ __forceinline__ int block_scan_incl(int v, int* wsum) {
    int lane = threadIdx.x & 31, wid = threadIdx.x >> 5;
    int x = v;
    #pragma unroll
    for (int off = 1; off < 32; off <<= 1) {
        int y = __shfl_up_sync(0xFFFFFFFFu, x, off);
        if (lane >= off) x += y;
    }
    if (lane == 31) wsum[wid] = x;
    __syncthreads();
    if (wid == 0) {
        int s = (lane < 32) ? wsum[lane] : 0;
        #pragma unroll
        for (int off = 1; off < 32; off <<= 1) {
            int y = __shfl_up_sync(0xFFFFFFFFu, s, off);
            if (lane >= off) s += y;
        }
        wsum[lane] = s;
    }
    __syncthreads();
    return x + (wid > 0 ? wsum[wid - 1] : 0);
}

// phase 1: per-block exclusive scan of g_count -> g_rowptr (local), block totals
__global__ __launch_bounds__(SCAN_BLK) void scan1_kernel(int n) {
    __shared__ int wsum[32];
    int idx = blockIdx.x * SCAN_BLK + threadIdx.x;
    int v = (idx < n) ? g_count[idx] : 0;
    int incl = block_scan_incl(v, wsum);
    if (idx < n) g_rowptr[idx] = incl - v;
    if (threadIdx.x == SCAN_BLK - 1) g_blocksum[blockIdx.x] = incl;
}

// phase 2: 1-block scan of block sums -> exclusive offsets (+ total at [nb])
__global__ __launch_bounds__(SCAN_BLK) void scan2_kernel(int nb) {
    __shared__ int wsum[32];
    int t = threadIdx.x;
    int v = (t < nb) ? g_blocksum[t] : 0;
    int incl = block_scan_incl(v, wsum);
    if (t < nb) g_blockoff[t] = incl - v;
    if (t == nb - 1) g_blockoff[nb] = incl;
}

// phase 3: add block offsets, init cursor, write rowptr[n]
__global__ __launch_bounds__(SCAN_BLK) void scan3_kernel(int n, int nb) {
    int idx = blockIdx.x * SCAN_BLK + threadIdx.x;
    if (idx < n) {
        int r = g_rowptr[idx] + g_blockoff[blockIdx.x];
        g_rowptr[idx] = r;
        g_cursor[idx] = r;
    }
    if (idx == 0) g_rowptr[n] = g_blockoff[nb];
}

__global__ void fill_kernel(const int* __restrict__ ei, int E, int n) {
    int e = blockIdx.x * blockDim.x + threadIdx.x;
    if (e < E) {
        int s = ei[e];
        int d = ei[(size_t)E + e];
        if ((unsigned)s < (unsigned)n && (unsigned)d < (unsigned)n) {
            int p = atomicAdd(&g_cursor[d], 1);
            g_csrc[p] = s;
            g_cw[p] = g_dinv[s] * g_dinv[d];
        }
    }
}

// ---------------- GEMM: C[n x 128] = A[n x 128] @ W[128 x 128] ----------------
__global__ __launch_bounds__(256) void gemm128_kernel(
    const float* __restrict__ A, const float* __restrict__ W,
    float* __restrict__ C, int n)
{
    __shared__ float Xs[32][136];   // transposed [k][row], pitch 136 kills store conflicts
    __shared__ float Ws[32][128];   // [k][col]
    int block_row = blockIdx.x * 128;
    int t = threadIdx.x;
    int tx = t & 15, ty = t >> 4;   // 16x16 thread grid; 8x8 micro-tile

    float acc[8][8];
    #pragma unroll
    for (int i = 0; i < 8; i++)
        #pragma unroll
        for (int j = 0; j < 8; j++) acc[i][j] = 0.0f;

    for (int kb = 0; kb < 128; kb += 32) {
        int chunk = t & 7;
        int rr = t >> 3;
        #pragma unroll
        for (int i = 0; i < 4; i++) {
            int r = rr + i * 32;
            int grow = block_row + r;
            float4 v = make_float4(0.f, 0.f, 0.f, 0.f);
            if (grow < n) v = *(const float4*)(A + (size_t)grow * 128 + kb + chunk * 4);
            Xs[chunk * 4 + 0][r] = v.x;
            Xs[chunk * 4 + 1][r] = v.y;
            Xs[chunk * 4 + 2][r] = v.z;
            Xs[chunk * 4 + 3][r] = v.w;
        }
        #pragma unroll
        for (int i = 0; i < 4; i++) {
            int idx = t + i * 256;
            int k = idx >> 5;
            int c = (idx & 31) << 2;
            *(float4*)&Ws[k][c] = *(const float4*)(W + (size_t)(kb + k) * 128 + c);
        }
        __syncthreads();

        #pragma unroll
        for (int k = 0; k < 32; k++) {
            float a[8], b[8];
            *(float4*)&a[0] = *(const float4*)&Xs[k][ty * 8];
            *(float4*)&a[4] = *(const float4*)&Xs[k][ty * 8 + 4];
            *(float4*)&b[0] = *(const float4*)&Ws[k][tx * 8];
            *(float4*)&b[4] = *(const float4*)&Ws[k][tx * 8 + 4];
            #pragma unroll
            for (int i = 0; i < 8; i++)
                #pragma unroll
                for (int j = 0; j < 8; j++)
                    acc[i][j] = fmaf(a[i], b[j], acc[i][j]);
        }
        __syncthreads();
    }

    #pragma unroll
    for (int i = 0; i < 8; i++) {
        int grow = block_row + ty * 8 + i;
        if (grow < n) {
            *(float4*)(C + (size_t)grow * 128 + tx * 8) =
                make_float4(acc[i][0], acc[i][1], acc[i][2], acc[i][3]);
            *(float4*)(C + (size_t)grow * 128 + tx * 8 + 4) =
                make_float4(acc[i][4], acc[i][5], acc[i][6], acc[i][7]);
        }
    }
}

// ---------------- aggregation: out[i] = relu(sum_{e in CSC(i)} h[src]*w + h[i]*dinv^2 + b) ----
__global__ __launch_bounds__(256) void aggregate_kernel(
    const float* __restrict__ h, const float* __restrict__ bias,
    float* __restrict__ out, int n)
{
    int warp = (blockIdx.x * blockDim.x + threadIdx.x) >> 5;
    int lane = threadIdx.x & 31;
    if (warp >= n) return;
    int i = warp;

    float di = g_dinv[i];
    float w0 = di * di;
    float4 v = ((const float4*)(h + (size_t)i * 128))[lane];
    float4 acc  = make_float4(v.x * w0, v.y * w0, v.z * w0, v.w * w0);
    float4 acc2 = make_float4(0.f, 0.f, 0.f, 0.f);

    int e0 = g_rowptr[i], e1 = g_rowptr[i + 1];
    int e = e0;
    for (; e + 1 < e1; e += 2) {
        int s0 = g_csrc[e];     float w_0 = g_cw[e];
        int s1 = g_csrc[e + 1]; float w_1 = g_cw[e + 1];
        float4 h0 = ((const float4*)(h + (size_t)s0 * 128))[lane];
        float4 h1 = ((const float4*)(h + (size_t)s1 * 128))[lane];
        acc.x  = fmaf(h0.x, w_0, acc.x);  acc.y  = fmaf(h0.y, w_0, acc.y);
        acc.z  = fmaf(h0.z, w_0, acc.z);  acc.w  = fmaf(h0.w, w_0, acc.w);
        acc2.x = fmaf(h1.x, w_1, acc2.x); acc2.y = fmaf(h1.y, w_1, acc2.y);
        acc2.z = fmaf(h1.z, w_1, acc2.z); acc2.w = fmaf(h1.w, w_1, acc2.w);
    }
    if (e < e1) {
        int s0 = g_csrc[e]; float w_0 = g_cw[e];
        float4 h0 = ((const float4*)(h + (size_t)s0 * 128))[lane];
        acc.x = fmaf(h0.x, w_0, acc.x); acc.y = fmaf(h0.y, w_0, acc.y);
        acc.z = fmaf(h0.z, w_0, acc.z); acc.w = fmaf(h0.w, w_0, acc.w);
    }
    acc.x += acc2.x; acc.y += acc2.y; acc.z += acc2.z; acc.w += acc2.w;

    float4 bb = ((const float4*)bias)[lane];
    acc.x = fmaxf(acc.x + bb.x, 0.0f);
    acc.y = fmaxf(acc.y + bb.y, 0.0f);
    acc.z = fmaxf(acc.z + bb.z, 0.0f);
    acc.w = fmaxf(acc.w + bb.w, 0.0f);
    ((float4*)(out + (size_t)i * 128))[lane] = acc;
}

// ---------------- decode: out[e] = dot(z[s], z[d]) ----------------
__global__ __launch_bounds__(256) void decode_kernel(
    const float* __restrict__ z, const int* __restrict__ eli,
    float* __restrict__ out, int el)
{
    int warp = (blockIdx.x * blockDim.x + threadIdx.x) >> 5;
    int lane = threadIdx.x & 31;
    if (warp >= el) return;
    int s = eli[warp];
    int d = eli[(size_t)el + warp];
    float4 a = ((const float4*)(z + (size_t)s * 128))[lane];
    float4 b = ((const float4*)(z + (size_t)d * 128))[lane];
    float p = a.x * b.x + a.y * b.y + a.z * b.z + a.w * b.w;
    #pragma unroll
    for (int off = 16; off; off >>= 1) p += __shfl_down_sync(0xFFFFFFFFu, p, off);
    if (lane == 0) out[warp] = p;
}

// ---------------- launch ----------------
extern "C" void kernel_launch(void* const* d_in, const int* in_sizes, int n_in,
                              void* d_out, int out_size)
{
    const float* x   = (const float*)d_in[0];
    const int*   ei  = (const int*)d_in[1];    // int64 tensors arrive as int32
    const int*   eli = (const int*)d_in[2];
    const float* W1  = (const float*)d_in[3];
    const float* b1  = (const float*)d_in[4];
    const float* W2  = (const float*)d_in[5];
    const float* b2  = (const float*)d_in[6];
    float* out = (float*)d_out;

    int n  = in_sizes[0] / DD;      // nodes
    int E  = in_sizes[1] / 2;       // edges
    int el = in_sizes[2] / 2;       // label edges

    float* h = nullptr; float* z = nullptr;
    cudaGetSymbolAddress((void**)&h, g_h);
    cudaGetSymbolAddress((void**)&z, g_z);

    const int T = 256;
    int nb_n = (n + T - 1) / T;
    int nb_e = (E + T - 1) / T;
    int nb_warpN = (n * 32 + T - 1) / T;   // one warp per node
    int nb_warpL = (el * 32 + T - 1) / T;  // one warp per label edge
    int nb_gemm = (n + 127) / 128;
    int nb_scan = (n + SCAN_BLK - 1) / SCAN_BLK;

    // graph preprocessing (shared by both layers)
    zero_count_kernel<<<nb_n, T>>>(n);
    count_kernel<<<nb_e, T>>>(ei, E, n);
    dinv_kernel<<<nb_n, T>>>(n);
    scan1_kernel<<<nb_scan, SCAN_BLK>>>(n);
    scan2_kernel<<<1, SCAN_BLK>>>(nb_scan);
    scan3_kernel<<<nb_scan, SCAN_BLK>>>(n, nb_scan);
    fill_kernel<<<nb_e, T>>>(ei, E, n);

    // layer 1: h = x@W1 ; z = relu(agg(h) + b1)
    gemm128_kernel<<<nb_gemm, T>>>(x, W1, h, n);
    aggregate_kernel<<<nb_warpN, T>>>(h, b1, z, n);

    // layer 2: h = z@W2 ; z = relu(agg(h) + b2)
    gemm128_kernel<<<nb_gemm, T>>>(z, W2, h, n);
    aggregate_kernel<<<nb_warpN, T>>>(h, b2, z, n);

    // decode
    decode_kernel<<<nb_warpL, T>>>(z, eli, out, el);
}

// round 5
// speedup vs baseline: 1.5045x; 1.3163x over previous
#include <cuda_runtime.h>
#include <cuda_bf16.h>
#include <cstdint>

#define NN 100000
#define EE 1600000
#define DD 128
#define SCAN_BLK 1024
#define GPITCH 136   // bf16 elements per smem row (128 + 8 pad -> conflict-free ldmatrix)

// ---------------- scratch (static device arrays; no allocation) ----------------
__device__ float g_h[(size_t)NN * DD];
__device__ float g_z[(size_t)NN * DD];
__device__ int   g_count[NN];
__device__ int   g_rowptr[NN + 1];
__device__ int   g_cursor[NN];
__device__ float g_dinv[NN];
__device__ int   g_csrc[EE];
__device__ float g_cw[EE];
__device__ int   g_blocksum[1024];
__device__ int   g_blockoff[1025];
// bf16 split of W1^T / W2^T : [n][k] layout (row = output col, k contiguous)
__device__ __nv_bfloat16 g_w1hi[DD * DD];
__device__ __nv_bfloat16 g_w1lo[DD * DD];
__device__ __nv_bfloat16 g_w2hi[DD * DD];
__device__ __nv_bfloat16 g_w2lo[DD * DD];

__device__ __forceinline__ uint32_t smem_u32(const void* p) {
    uint32_t a;
    asm("{ .reg .u64 t; cvta.to.shared.u64 t, %1; cvt.u32.u64 %0, t; }" : "=r"(a) : "l"(p));
    return a;
}

// ---------------- graph preprocessing ----------------
__global__ void zero_count_kernel(int n) {
    int i = blockIdx.x * blockDim.x + threadIdx.x;
    if (i < n) g_count[i] = 0;
}

__global__ void count_kernel(const int* __restrict__ ei, int E, int n) {
    int e = blockIdx.x * blockDim.x + threadIdx.x;
    if (e < E) {
        int d = ei[(size_t)E + e];
        if ((unsigned)d < (unsigned)n) atomicAdd(&g_count[d], 1);
    }
}

__global__ void dinv_kernel(int n) {
    int i = blockIdx.x * blockDim.x + threadIdx.x;
    if (i < n) g_dinv[i] = rsqrtf((float)g_count[i] + 1.0f);
}

__device__ __forceinline__ int block_scan_incl(int v, int* wsum) {
    int lane = threadIdx.x & 31, wid = threadIdx.x >> 5;
    int x = v;
    #pragma unroll
    for (int off = 1; off < 32; off <<= 1) {
        int y = __shfl_up_sync(0xFFFFFFFFu, x, off);
        if (lane >= off) x += y;
    }
    if (lane == 31) wsum[wid] = x;
    __syncthreads();
    if (wid == 0) {
        int s = wsum[lane];
        #pragma unroll
        for (int off = 1; off < 32; off <<= 1) {
            int y = __shfl_up_sync(0xFFFFFFFFu, s, off);
            if (lane >= off) s += y;
        }
        wsum[lane] = s;
    }
    __syncthreads();
    return x + (wid > 0 ? wsum[wid - 1] : 0);
}

__global__ __launch_bounds__(SCAN_BLK) void scan1_kernel(int n) {
    __shared__ int wsum[32];
    int idx = blockIdx.x * SCAN_BLK + threadIdx.x;
    int v = (idx < n) ? g_count[idx] : 0;
    int incl = block_scan_incl(v, wsum);
    if (idx < n) g_rowptr[idx] = incl - v;
    if (threadIdx.x == SCAN_BLK - 1) g_blocksum[blockIdx.x] = incl;
}

__global__ __launch_bounds__(SCAN_BLK) void scan2_kernel(int nb) {
    __shared__ int wsum[32];
    int t = threadIdx.x;
    int v = (t < nb) ? g_blocksum[t] : 0;
    int incl = block_scan_incl(v, wsum);
    if (t < nb) g_blockoff[t] = incl - v;
    if (t == nb - 1) g_blockoff[nb] = incl;
}

__global__ __launch_bounds__(SCAN_BLK) void scan3_kernel(int n, int nb) {
    int idx = blockIdx.x * SCAN_BLK + threadIdx.x;
    if (idx < n) {
        int r = g_rowptr[idx] + g_blockoff[blockIdx.x];
        g_rowptr[idx] = r;
        g_cursor[idx] = r;
    }
    if (idx == 0) g_rowptr[n] = g_blockoff[nb];
}

__global__ void fill_kernel(const int* __restrict__ ei, int E, int n) {
    int e = blockIdx.x * blockDim.x + threadIdx.x;
    if (e < E) {
        int s = ei[e];
        int d = ei[(size_t)E + e];
        if ((unsigned)s < (unsigned)n && (unsigned)d < (unsigned)n) {
            int p = atomicAdd(&g_cursor[d], 1);
            g_csrc[p] = s;
            g_cw[p] = g_dinv[s] * g_dinv[d];
        }
    }
}

// ---------------- W split: Wt_hi/lo[n][k] = split(W[k][n]) ----------------
__global__ void convert_w_kernel(const float* __restrict__ W1, const float* __restrict__ W2) {
    int i = blockIdx.x * blockDim.x + threadIdx.x;
    if (i >= DD * DD) return;
    int nn = i >> 7, kk = i & 127;
    float w1 = W1[kk * DD + nn];
    __nv_bfloat16 h1 = __float2bfloat16(w1);
    g_w1hi[nn * DD + kk] = h1;
    g_w1lo[nn * DD + kk] = __float2bfloat16(w1 - __bfloat162float(h1));
    float w2 = W2[kk * DD + nn];
    __nv_bfloat16 h2 = __float2bfloat16(w2);
    g_w2hi[nn * DD + kk] = h2;
    g_w2lo[nn * DD + kk] = __float2bfloat16(w2 - __bfloat162float(h2));
}

// ---------------- mma.sync helpers ----------------
__device__ __forceinline__ void ldsm_x4(uint32_t addr, uint32_t& r0, uint32_t& r1, uint32_t& r2, uint32_t& r3) {
    asm volatile("ldmatrix.sync.aligned.m8n8.x4.shared.b16 {%0,%1,%2,%3}, [%4];"
        : "=r"(r0), "=r"(r1), "=r"(r2), "=r"(r3) : "r"(addr));
}
__device__ __forceinline__ void mma_bf16(float* c, uint32_t a0, uint32_t a1, uint32_t a2, uint32_t a3,
                                         uint32_t b0, uint32_t b1) {
    asm volatile("mma.sync.aligned.m16n8k16.row.col.f32.bf16.bf16.f32 "
        "{%0,%1,%2,%3}, {%4,%5,%6,%7}, {%8,%9}, {%0,%1,%2,%3};"
        : "+f"(c[0]), "+f"(c[1]), "+f"(c[2]), "+f"(c[3])
        : "r"(a0), "r"(a1), "r"(a2), "r"(a3), "r"(b0), "r"(b1));
}

// ---------------- GEMM via mma.sync: C[n x 128] = A[n x 128] @ W[128 x 128] ----------------
// 3-term bf16 split: C = Ahi*Whi + Alo*Whi + Ahi*Wlo  (fp32 accumulate)
#define GSM_BYTES (4 * 128 * GPITCH * 2)

__global__ __launch_bounds__(256) void gemm_mma_kernel(
    const float* __restrict__ A,
    const __nv_bfloat16* __restrict__ Wthi,
    const __nv_bfloat16* __restrict__ Wtlo,
    float* __restrict__ C, int n)
{
    extern __shared__ __align__(16) __nv_bfloat16 sm[];
    __nv_bfloat16* Xhi = sm;                       // 128 x GPITCH
    __nv_bfloat16* Xlo = Xhi + 128 * GPITCH;
    __nv_bfloat16* Whi = Xlo + 128 * GPITCH;
    __nv_bfloat16* Wlo = Whi + 128 * GPITCH;

    int tid = threadIdx.x;
    int w = tid >> 5, l = tid & 31;
    int block_row = blockIdx.x * 128;

    // ---- load + split X tile (128 x 128 fp32 -> bf16 hi/lo) ----
    #pragma unroll
    for (int it = 0; it < 16; it++) {
        int idx = tid + it * 256;       // float4 index 0..4095
        int r = idx >> 5;
        int c = (idx & 31) * 4;
        int grow = block_row + r;
        float4 v = make_float4(0.f, 0.f, 0.f, 0.f);
        if (grow < n) v = *(const float4*)(A + (size_t)grow * 128 + c);
        __nv_bfloat16 h0 = __float2bfloat16(v.x), h1 = __float2bfloat16(v.y);
        __nv_bfloat16 h2 = __float2bfloat16(v.z), h3 = __float2bfloat16(v.w);
        *(__nv_bfloat162*)&Xhi[r * GPITCH + c]     = __nv_bfloat162(h0, h1);
        *(__nv_bfloat162*)&Xhi[r * GPITCH + c + 2] = __nv_bfloat162(h2, h3);
        *(__nv_bfloat162*)&Xlo[r * GPITCH + c] =
            __nv_bfloat162(__float2bfloat16(v.x - __bfloat162float(h0)),
                           __float2bfloat16(v.y - __bfloat162float(h1)));
        *(__nv_bfloat162*)&Xlo[r * GPITCH + c + 2] =
            __nv_bfloat162(__float2bfloat16(v.z - __bfloat162float(h2)),
                           __float2bfloat16(v.w - __bfloat162float(h3)));
    }
    // ---- load W hi/lo ([n][k] bf16, contiguous) ----
    #pragma unroll
    for (int it = 0; it < 32; it++) {
        int idx = tid + it * 256;       // u32 index 0..8191
        int r = idx >> 6;
        int c = (idx & 63) * 2;
        *(uint32_t*)&Whi[r * GPITCH + c] = *(const uint32_t*)(Wthi + (size_t)r * 128 + c);
        *(uint32_t*)&Wlo[r * GPITCH + c] = *(const uint32_t*)(Wtlo + (size_t)r * 128 + c);
    }
    __syncthreads();

    uint32_t sbase = smem_u32(sm);
    // A fragment addresses: lane -> row = w*16 + (l&15), col = (l>>4)*8  (+kk*16)
    uint32_t a_off = (uint32_t)(((w * 16 + (l & 15)) * GPITCH + (l >> 4) * 8) * 2);
    uint32_t ahi_addr = sbase + a_off;
    uint32_t alo_addr = sbase + (uint32_t)(128 * GPITCH * 2) + a_off;
    // B fragment addresses: lane -> row = (l&7) + ((l>>4)<<3) (+j2*16), col = ((l>>3)&1)*8 (+kk*16)
    uint32_t b_off = (uint32_t)((((l & 7) + ((l >> 4) << 3)) * GPITCH + ((l >> 3) & 1) * 8) * 2);
    uint32_t bhi_addr = sbase + (uint32_t)(2 * 128 * GPITCH * 2) + b_off;
    uint32_t blo_addr = sbase + (uint32_t)(3 * 128 * GPITCH * 2) + b_off;

    float acc[16][4];
    #pragma unroll
    for (int j = 0; j < 16; j++)
        #pragma unroll
        for (int q = 0; q < 4; q++) acc[j][q] = 0.0f;

    #pragma unroll
    for (int kk = 0; kk < 8; kk++) {
        uint32_t ka = kk * 32;   // 16 bf16 = 32 bytes
        uint32_t ah0, ah1, ah2, ah3, al0, al1, al2, al3;
        ldsm_x4(ahi_addr + ka, ah0, ah1, ah2, ah3);
        ldsm_x4(alo_addr + ka, al0, al1, al2, al3);
        #pragma unroll
        for (int j2 = 0; j2 < 8; j2++) {
            uint32_t boff = (uint32_t)(j2 * 16 * GPITCH * 2) + ka;
            uint32_t bh0, bh1, bh2, bh3, bl0, bl1, bl2, bl3;
            ldsm_x4(bhi_addr + boff, bh0, bh1, bh2, bh3);
            ldsm_x4(blo_addr + boff, bl0, bl1, bl2, bl3);
            mma_bf16(acc[2 * j2],     ah0, ah1, ah2, ah3, bh0, bh1);
            mma_bf16(acc[2 * j2],     al0, al1, al2, al3, bh0, bh1);
            mma_bf16(acc[2 * j2],     ah0, ah1, ah2, ah3, bl0, bl1);
            mma_bf16(acc[2 * j2 + 1], ah0, ah1, ah2, ah3, bh2, bh3);
            mma_bf16(acc[2 * j2 + 1], al0, al1, al2, al3, bh2, bh3);
            mma_bf16(acc[2 * j2 + 1], ah0, ah1, ah2, ah3, bl2, bl3);
        }
    }

    // ---- epilogue: fragment -> global ----
    int g = l >> 2, t = l & 3;
    int row0 = block_row + w * 16 + g;
    int row1 = row0 + 8;
    #pragma unroll
    for (int j = 0; j < 16; j++) {
        int col = j * 8 + t * 2;
        if (row0 < n) *(float2*)(C + (size_t)row0 * 128 + col) = make_float2(acc[j][0], acc[j][1]);
        if (row1 < n) *(float2*)(C + (size_t)row1 * 128 + col) = make_float2(acc[j][2], acc[j][3]);
    }
}

// ---------------- aggregation ----------------
__global__ __launch_bounds__(256) void aggregate_kernel(
    const float* __restrict__ h, const float* __restrict__ bias,
    float* __restrict__ out, int n)
{
    int warp = (blockIdx.x * blockDim.x + threadIdx.x) >> 5;
    int lane = threadIdx.x & 31;
    if (warp >= n) return;
    int i = warp;

    float di = g_dinv[i];
    float w0 = di * di;
    float4 v = ((const float4*)(h + (size_t)i * 128))[lane];
    float4 acc  = make_float4(v.x * w0, v.y * w0, v.z * w0, v.w * w0);
    float4 acc2 = make_float4(0.f, 0.f, 0.f, 0.f);

    int e0 = g_rowptr[i], e1 = g_rowptr[i + 1];
    int e = e0;
    for (; e + 1 < e1; e += 2) {
        int s0 = g_csrc[e];     float w_0 = g_cw[e];
        int s1 = g_csrc[e + 1]; float w_1 = g_cw[e + 1];
        float4 h0 = ((const float4*)(h + (size_t)s0 * 128))[lane];
        float4 h1 = ((const float4*)(h + (size_t)s1 * 128))[lane];
        acc.x  = fmaf(h0.x, w_0, acc.x);  acc.y  = fmaf(h0.y, w_0, acc.y);
        acc.z  = fmaf(h0.z, w_0, acc.z);  acc.w  = fmaf(h0.w, w_0, acc.w);
        acc2.x = fmaf(h1.x, w_1, acc2.x); acc2.y = fmaf(h1.y, w_1, acc2.y);
        acc2.z = fmaf(h1.z, w_1, acc2.z); acc2.w = fmaf(h1.w, w_1, acc2.w);
    }
    if (e < e1) {
        int s0 = g_csrc[e]; float w_0 = g_cw[e];
        float4 h0 = ((const float4*)(h + (size_t)s0 * 128))[lane];
        acc.x = fmaf(h0.x, w_0, acc.x); acc.y = fmaf(h0.y, w_0, acc.y);
        acc.z = fmaf(h0.z, w_0, acc.z); acc.w = fmaf(h0.w, w_0, acc.w);
    }
    acc.x += acc2.x; acc.y += acc2.y; acc.z += acc2.z; acc.w += acc2.w;

    float4 bb = ((const float4*)bias)[lane];
    acc.x = fmaxf(acc.x + bb.x, 0.0f);
    acc.y = fmaxf(acc.y + bb.y, 0.0f);
    acc.z = fmaxf(acc.z + bb.z, 0.0f);
    acc.w = fmaxf(acc.w + bb.w, 0.0f);
    ((float4*)(out + (size_t)i * 128))[lane] = acc;
}

// ---------------- decode ----------------
__global__ __launch_bounds__(256) void decode_kernel(
    const float* __restrict__ z, const int* __restrict__ eli,
    float* __restrict__ out, int el)
{
    int warp = (blockIdx.x * blockDim.x + threadIdx.x) >> 5;
    int lane = threadIdx.x & 31;
    if (warp >= el) return;
    int s = eli[warp];
    int d = eli[(size_t)el + warp];
    float4 a = ((const float4*)(z + (size_t)s * 128))[lane];
    float4 b = ((const float4*)(z + (size_t)d * 128))[lane];
    float p = a.x * b.x + a.y * b.y + a.z * b.z + a.w * b.w;
    #pragma unroll
    for (int off = 16; off; off >>= 1) p += __shfl_down_sync(0xFFFFFFFFu, p, off);
    if (lane == 0) out[warp] = p;
}

// ---------------- launch ----------------
extern "C" void kernel_launch(void* const* d_in, const int* in_sizes, int n_in,
                              void* d_out, int out_size)
{
    const float* x   = (const float*)d_in[0];
    const int*   ei  = (const int*)d_in[1];    // int64 tensors arrive as int32
    const int*   eli = (const int*)d_in[2];
    const float* W1  = (const float*)d_in[3];
    const float* b1  = (const float*)d_in[4];
    const float* W2  = (const float*)d_in[5];
    const float* b2  = (const float*)d_in[6];
    float* out = (float*)d_out;

    int n  = in_sizes[0] / DD;
    int E  = in_sizes[1] / 2;
    int el = in_sizes[2] / 2;

    float* h = nullptr; float* z = nullptr;
    __nv_bfloat16 *w1hi = nullptr, *w1lo = nullptr, *w2hi = nullptr, *w2lo = nullptr;
    cudaGetSymbolAddress((void**)&h, g_h);
    cudaGetSymbolAddress((void**)&z, g_z);
    cudaGetSymbolAddress((void**)&w1hi, g_w1hi);
    cudaGetSymbolAddress((void**)&w1lo, g_w1lo);
    cudaGetSymbolAddress((void**)&w2hi, g_w2hi);
    cudaGetSymbolAddress((void**)&w2lo, g_w2lo);

    cudaFuncSetAttribute(gemm_mma_kernel, cudaFuncAttributeMaxDynamicSharedMemorySize, GSM_BYTES);

    const int T = 256;
    int nb_n = (n + T - 1) / T;
    int nb_e = (E + T - 1) / T;
    int nb_warpN = (n * 32 + T - 1) / T;
    int nb_warpL = (el * 32 + T - 1) / T;
    int nb_gemm = (n + 127) / 128;
    int nb_scan = (n + SCAN_BLK - 1) / SCAN_BLK;

    // graph preprocessing
    zero_count_kernel<<<nb_n, T>>>(n);
    count_kernel<<<nb_e, T>>>(ei, E, n);
    dinv_kernel<<<nb_n, T>>>(n);
    scan1_kernel<<<nb_scan, SCAN_BLK>>>(n);
    scan2_kernel<<<1, SCAN_BLK>>>(nb_scan);
    scan3_kernel<<<nb_scan, SCAN_BLK>>>(n, nb_scan);
    fill_kernel<<<nb_e, T>>>(ei, E, n);
    convert_w_kernel<<<(DD * DD + 255) / 256, 256>>>(W1, W2);

    // layer 1: h = x@W1 ; z = relu(agg(h) + b1)
    gemm_mma_kernel<<<nb_gemm, T, GSM_BYTES>>>(x, w1hi, w1lo, h, n);
    aggregate_kernel<<<nb_warpN, T>>>(h, b1, z, n);

    // layer 2: h = z@W2 ; z = relu(agg(h) + b2)
    gemm_mma_kernel<<<nb_gemm, T, GSM_BYTES>>>(z, w2hi, w2lo, h, n);
    aggregate_kernel<<<nb_warpN, T>>>(h, b2, z, n);

    // decode
    decode_kernel<<<nb_warpL, T>>>(z, eli, out, el);
}

// round 6
// speedup vs baseline: 1.7274x; 1.1481x over previous
#include <cuda_runtime.h>
#include <cuda_bf16.h>
#include <cuda_fp16.h>
#include <cstdint>

#define NN 100000
#define EE 1600000
#define DD 128
#define SCAN_BLK 1024
#define GPITCH 136   // bf16 elements per smem row (128 + 8 pad -> conflict-free ldmatrix)

// ---------------- scratch (static device arrays; no allocation) ----------------
__device__ __half g_h[(size_t)NN * DD];   // GEMM output (fp16), aggregation input
__device__ float  g_z[(size_t)NN * DD];   // aggregation output (fp32)
__device__ int   g_count[NN];
__device__ int   g_rowptr[NN + 1];
__device__ int   g_cursor[NN];
__device__ float g_dinv[NN];
__device__ int   g_csrc[EE];
__device__ float g_cw[EE];
__device__ int   g_blocksum[1024];
__device__ int   g_blockoff[1025];
// bf16 split of W1^T / W2^T : [n][k] layout (row = output col, k contiguous)
__device__ __nv_bfloat16 g_w1hi[DD * DD];
__device__ __nv_bfloat16 g_w1lo[DD * DD];
__device__ __nv_bfloat16 g_w2hi[DD * DD];
__device__ __nv_bfloat16 g_w2lo[DD * DD];

__device__ __forceinline__ uint32_t smem_u32(const void* p) {
    uint32_t a;
    asm("{ .reg .u64 t; cvta.to.shared.u64 t, %1; cvt.u32.u64 %0, t; }" : "=r"(a) : "l"(p));
    return a;
}

// ---------------- graph preprocessing ----------------
__global__ void zero_count_kernel(int n) {
    int i = blockIdx.x * blockDim.x + threadIdx.x;
    if (i < n) g_count[i] = 0;
}

__global__ void count_kernel(const int* __restrict__ ei, int E, int n) {
    int e = blockIdx.x * blockDim.x + threadIdx.x;
    if (e < E) {
        int d = ei[(size_t)E + e];
        if ((unsigned)d < (unsigned)n) atomicAdd(&g_count[d], 1);
    }
}

__global__ void dinv_kernel(int n) {
    int i = blockIdx.x * blockDim.x + threadIdx.x;
    if (i < n) g_dinv[i] = rsqrtf((float)g_count[i] + 1.0f);
}

__device__ __forceinline__ int block_scan_incl(int v, int* wsum) {
    int lane = threadIdx.x & 31, wid = threadIdx.x >> 5;
    int x = v;
    #pragma unroll
    for (int off = 1; off < 32; off <<= 1) {
        int y = __shfl_up_sync(0xFFFFFFFFu, x, off);
        if (lane >= off) x += y;
    }
    if (lane == 31) wsum[wid] = x;
    __syncthreads();
    if (wid == 0) {
        int s = wsum[lane];
        #pragma unroll
        for (int off = 1; off < 32; off <<= 1) {
            int y = __shfl_up_sync(0xFFFFFFFFu, s, off);
            if (lane >= off) s += y;
        }
        wsum[lane] = s;
    }
    __syncthreads();
    return x + (wid > 0 ? wsum[wid - 1] : 0);
}

__global__ __launch_bounds__(SCAN_BLK) void scan1_kernel(int n) {
    __shared__ int wsum[32];
    int idx = blockIdx.x * SCAN_BLK + threadIdx.x;
    int v = (idx < n) ? g_count[idx] : 0;
    int incl = block_scan_incl(v, wsum);
    if (idx < n) g_rowptr[idx] = incl - v;
    if (threadIdx.x == SCAN_BLK - 1) g_blocksum[blockIdx.x] = incl;
}

__global__ __launch_bounds__(SCAN_BLK) void scan2_kernel(int nb) {
    __shared__ int wsum[32];
    int t = threadIdx.x;
    int v = (t < nb) ? g_blocksum[t] : 0;
    int incl = block_scan_incl(v, wsum);
    if (t < nb) g_blockoff[t] = incl - v;
    if (t == nb - 1) g_blockoff[nb] = incl;
}

__global__ __launch_bounds__(SCAN_BLK) void scan3_kernel(int n, int nb) {
    int idx = blockIdx.x * SCAN_BLK + threadIdx.x;
    if (idx < n) {
        int r = g_rowptr[idx] + g_blockoff[blockIdx.x];
        g_rowptr[idx] = r;
        g_cursor[idx] = r;
    }
    if (idx == 0) g_rowptr[n] = g_blockoff[nb];
}

__global__ void fill_kernel(const int* __restrict__ ei, int E, int n) {
    int e = blockIdx.x * blockDim.x + threadIdx.x;
    if (e < E) {
        int s = ei[e];
        int d = ei[(size_t)E + e];
        if ((unsigned)s < (unsigned)n && (unsigned)d < (unsigned)n) {
            int p = atomicAdd(&g_cursor[d], 1);
            g_csrc[p] = s;
            g_cw[p] = g_dinv[s] * g_dinv[d];
        }
    }
}

// ---------------- W split: Wt_hi/lo[n][k] = split(W[k][n]) ----------------
__global__ void convert_w_kernel(const float* __restrict__ W1, const float* __restrict__ W2) {
    int i = blockIdx.x * blockDim.x + threadIdx.x;
    if (i >= DD * DD) return;
    int nn = i >> 7, kk = i & 127;
    float w1 = W1[kk * DD + nn];
    __nv_bfloat16 h1 = __float2bfloat16(w1);
    g_w1hi[nn * DD + kk] = h1;
    g_w1lo[nn * DD + kk] = __float2bfloat16(w1 - __bfloat162float(h1));
    float w2 = W2[kk * DD + nn];
    __nv_bfloat16 h2 = __float2bfloat16(w2);
    g_w2hi[nn * DD + kk] = h2;
    g_w2lo[nn * DD + kk] = __float2bfloat16(w2 - __bfloat162float(h2));
}

// ---------------- mma.sync helpers ----------------
__device__ __forceinline__ void ldsm_x4(uint32_t addr, uint32_t& r0, uint32_t& r1, uint32_t& r2, uint32_t& r3) {
    asm volatile("ldmatrix.sync.aligned.m8n8.x4.shared.b16 {%0,%1,%2,%3}, [%4];"
        : "=r"(r0), "=r"(r1), "=r"(r2), "=r"(r3) : "r"(addr));
}
__device__ __forceinline__ void mma_bf16(float* c, uint32_t a0, uint32_t a1, uint32_t a2, uint32_t a3,
                                         uint32_t b0, uint32_t b1) {
    asm volatile("mma.sync.aligned.m16n8k16.row.col.f32.bf16.bf16.f32 "
        "{%0,%1,%2,%3}, {%4,%5,%6,%7}, {%8,%9}, {%0,%1,%2,%3};"
        : "+f"(c[0]), "+f"(c[1]), "+f"(c[2]), "+f"(c[3])
        : "r"(a0), "r"(a1), "r"(a2), "r"(a3), "r"(b0), "r"(b1));
}

// ---------------- GEMM via mma.sync: C[n x 128] = A[n x 128] @ W[128 x 128] -> fp16 ----------
// 3-term bf16 split: C = Ahi*Whi + Alo*Whi + Ahi*Wlo  (fp32 accumulate)
#define GSM_BYTES (4 * 128 * GPITCH * 2)

__global__ __launch_bounds__(256) void gemm_mma_kernel(
    const float* __restrict__ A,
    const __nv_bfloat16* __restrict__ Wthi,
    const __nv_bfloat16* __restrict__ Wtlo,
    __half* __restrict__ C, int n)
{
    extern __shared__ __align__(16) __nv_bfloat16 sm[];
    __nv_bfloat16* Xhi = sm;                       // 128 x GPITCH
    __nv_bfloat16* Xlo = Xhi + 128 * GPITCH;
    __nv_bfloat16* Whi = Xlo + 128 * GPITCH;
    __nv_bfloat16* Wlo = Whi + 128 * GPITCH;

    int tid = threadIdx.x;
    int w = tid >> 5, l = tid & 31;
    int block_row = blockIdx.x * 128;

    // ---- load + split X tile (128 x 128 fp32 -> bf16 hi/lo) ----
    #pragma unroll
    for (int it = 0; it < 16; it++) {
        int idx = tid + it * 256;       // float4 index 0..4095
        int r = idx >> 5;
        int c = (idx & 31) * 4;
        int grow = block_row + r;
        float4 v = make_float4(0.f, 0.f, 0.f, 0.f);
        if (grow < n) v = *(const float4*)(A + (size_t)grow * 128 + c);
        __nv_bfloat16 h0 = __float2bfloat16(v.x), h1 = __float2bfloat16(v.y);
        __nv_bfloat16 h2 = __float2bfloat16(v.z), h3 = __float2bfloat16(v.w);
        *(__nv_bfloat162*)&Xhi[r * GPITCH + c]     = __nv_bfloat162(h0, h1);
        *(__nv_bfloat162*)&Xhi[r * GPITCH + c + 2] = __nv_bfloat162(h2, h3);
        *(__nv_bfloat162*)&Xlo[r * GPITCH + c] =
            __nv_bfloat162(__float2bfloat16(v.x - __bfloat162float(h0)),
                           __float2bfloat16(v.y - __bfloat162float(h1)));
        *(__nv_bfloat162*)&Xlo[r * GPITCH + c + 2] =
            __nv_bfloat162(__float2bfloat16(v.z - __bfloat162float(h2)),
                           __float2bfloat16(v.w - __bfloat162float(h3)));
    }
    // ---- load W hi/lo ([n][k] bf16, contiguous) ----
    #pragma unroll
    for (int it = 0; it < 32; it++) {
        int idx = tid + it * 256;       // u32 index 0..8191
        int r = idx >> 6;
        int c = (idx & 63) * 2;
        *(uint32_t*)&Whi[r * GPITCH + c] = *(const uint32_t*)(Wthi + (size_t)r * 128 + c);
        *(uint32_t*)&Wlo[r * GPITCH + c] = *(const uint32_t*)(Wtlo + (size_t)r * 128 + c);
    }
    __syncthreads();

    uint32_t sbase = smem_u32(sm);
    uint32_t a_off = (uint32_t)(((w * 16 + (l & 15)) * GPITCH + (l >> 4) * 8) * 2);
    uint32_t ahi_addr = sbase + a_off;
    uint32_t alo_addr = sbase + (uint32_t)(128 * GPITCH * 2) + a_off;
    uint32_t b_off = (uint32_t)((((l & 7) + ((l >> 4) << 3)) * GPITCH + ((l >> 3) & 1) * 8) * 2);
    uint32_t bhi_addr = sbase + (uint32_t)(2 * 128 * GPITCH * 2) + b_off;
    uint32_t blo_addr = sbase + (uint32_t)(3 * 128 * GPITCH * 2) + b_off;

    float acc[16][4];
    #pragma unroll
    for (int j = 0; j < 16; j++)
        #pragma unroll
        for (int q = 0; q < 4; q++) acc[j][q] = 0.0f;

    #pragma unroll
    for (int kk = 0; kk < 8; kk++) {
        uint32_t ka = kk * 32;   // 16 bf16 = 32 bytes
        uint32_t ah0, ah1, ah2, ah3, al0, al1, al2, al3;
        ldsm_x4(ahi_addr + ka, ah0, ah1, ah2, ah3);
        ldsm_x4(alo_addr + ka, al0, al1, al2, al3);
        #pragma unroll
        for (int j2 = 0; j2 < 8; j2++) {
            uint32_t boff = (uint32_t)(j2 * 16 * GPITCH * 2) + ka;
            uint32_t bh0, bh1, bh2, bh3, bl0, bl1, bl2, bl3;
            ldsm_x4(bhi_addr + boff, bh0, bh1, bh2, bh3);
            ldsm_x4(blo_addr + boff, bl0, bl1, bl2, bl3);
            mma_bf16(acc[2 * j2],     ah0, ah1, ah2, ah3, bh0, bh1);
            mma_bf16(acc[2 * j2],     al0, al1, al2, al3, bh0, bh1);
            mma_bf16(acc[2 * j2],     ah0, ah1, ah2, ah3, bl0, bl1);
            mma_bf16(acc[2 * j2 + 1], ah0, ah1, ah2, ah3, bh2, bh3);
            mma_bf16(acc[2 * j2 + 1], al0, al1, al2, al3, bh2, bh3);
            mma_bf16(acc[2 * j2 + 1], ah0, ah1, ah2, ah3, bl2, bl3);
        }
    }

    // ---- epilogue: fragment -> global fp16 ----
    int g = l >> 2, t = l & 3;
    int row0 = block_row + w * 16 + g;
    int row1 = row0 + 8;
    #pragma unroll
    for (int j = 0; j < 16; j++) {
        int col = j * 8 + t * 2;
        if (row0 < n) *(__half2*)(C + (size_t)row0 * 128 + col) = __floats2half2_rn(acc[j][0], acc[j][1]);
        if (row1 < n) *(__half2*)(C + (size_t)row1 * 128 + col) = __floats2half2_rn(acc[j][2], acc[j][3]);
    }
}

// ---------------- aggregation: out[i] = relu(sum h16[src]*w + h16[i]*dinv^2 + b) ----------------
__device__ __forceinline__ float4 half4_to_float4(uint2 raw) {
    __half2 p0 = *reinterpret_cast<__half2*>(&raw.x);
    __half2 p1 = *reinterpret_cast<__half2*>(&raw.y);
    float2 f0 = __half22float2(p0), f1 = __half22float2(p1);
    return make_float4(f0.x, f0.y, f1.x, f1.y);
}

__global__ __launch_bounds__(256) void aggregate_kernel(
    const __half* __restrict__ h, const float* __restrict__ bias,
    float* __restrict__ out, int n)
{
    int warp = (blockIdx.x * blockDim.x + threadIdx.x) >> 5;
    int lane = threadIdx.x & 31;
    if (warp >= n) return;
    int i = warp;

    float di = g_dinv[i];
    float w0 = di * di;
    float4 v = half4_to_float4(((const uint2*)(h + (size_t)i * 128))[lane]);
    float4 acc  = make_float4(v.x * w0, v.y * w0, v.z * w0, v.w * w0);
    float4 acc2 = make_float4(0.f, 0.f, 0.f, 0.f);

    int e0 = g_rowptr[i], e1 = g_rowptr[i + 1];
    int e = e0;
    for (; e + 3 < e1; e += 4) {
        int s0 = g_csrc[e];     float w_0 = g_cw[e];
        int s1 = g_csrc[e + 1]; float w_1 = g_cw[e + 1];
        int s2 = g_csrc[e + 2]; float w_2 = g_cw[e + 2];
        int s3 = g_csrc[e + 3]; float w_3 = g_cw[e + 3];
        uint2 r0 = ((const uint2*)(h + (size_t)s0 * 128))[lane];
        uint2 r1 = ((const uint2*)(h + (size_t)s1 * 128))[lane];
        uint2 r2 = ((const uint2*)(h + (size_t)s2 * 128))[lane];
        uint2 r3 = ((const uint2*)(h + (size_t)s3 * 128))[lane];
        float4 h0 = half4_to_float4(r0), h1 = half4_to_float4(r1);
        float4 h2 = half4_to_float4(r2), h3 = half4_to_float4(r3);
        acc.x  = fmaf(h0.x, w_0, acc.x);  acc.y  = fmaf(h0.y, w_0, acc.y);
        acc.z  = fmaf(h0.z, w_0, acc.z);  acc.w  = fmaf(h0.w, w_0, acc.w);
        acc2.x = fmaf(h1.x, w_1, acc2.x); acc2.y = fmaf(h1.y, w_1, acc2.y);
        acc2.z = fmaf(h1.z, w_1, acc2.z); acc2.w = fmaf(h1.w, w_1, acc2.w);
        acc.x  = fmaf(h2.x, w_2, acc.x);  acc.y  = fmaf(h2.y, w_2, acc.y);
        acc.z  = fmaf(h2.z, w_2, acc.z);  acc.w  = fmaf(h2.w, w_2, acc.w);
        acc2.x = fmaf(h3.x, w_3, acc2.x); acc2.y = fmaf(h3.y, w_3, acc2.y);
        acc2.z = fmaf(h3.z, w_3, acc2.z); acc2.w = fmaf(h3.w, w_3, acc2.w);
    }
    for (; e < e1; e++) {
        int s0 = g_csrc[e]; float w_0 = g_cw[e];
        float4 h0 = half4_to_float4(((const uint2*)(h + (size_t)s0 * 128))[lane]);
        acc.x = fmaf(h0.x, w_0, acc.x); acc.y = fmaf(h0.y, w_0, acc.y);
        acc.z = fmaf(h0.z, w_0, acc.z); acc.w = fmaf(h0.w, w_0, acc.w);
    }
    acc.x += acc2.x; acc.y += acc2.y; acc.z += acc2.z; acc.w += acc2.w;

    float4 bb = ((const float4*)bias)[lane];
    acc.x = fmaxf(acc.x + bb.x, 0.0f);
    acc.y = fmaxf(acc.y + bb.y, 0.0f);
    acc.z = fmaxf(acc.z + bb.z, 0.0f);
    acc.w = fmaxf(acc.w + bb.w, 0.0f);
    ((float4*)(out + (size_t)i * 128))[lane] = acc;
}

// ---------------- decode ----------------
__global__ __launch_bounds__(256) void decode_kernel(
    const float* __restrict__ z, const int* __restrict__ eli,
    float* __restrict__ out, int el)
{
    int warp = (blockIdx.x * blockDim.x + threadIdx.x) >> 5;
    int lane = threadIdx.x & 31;
    if (warp >= el) return;
    int s = eli[warp];
    int d = eli[(size_t)el + warp];
    float4 a = ((const float4*)(z + (size_t)s * 128))[lane];
    float4 b = ((const float4*)(z + (size_t)d * 128))[lane];
    float p = a.x * b.x + a.y * b.y + a.z * b.z + a.w * b.w;
    #pragma unroll
    for (int off = 16; off; off >>= 1) p += __shfl_down_sync(0xFFFFFFFFu, p, off);
    if (lane == 0) out[warp] = p;
}

// ---------------- launch ----------------
extern "C" void kernel_launch(void* const* d_in, const int* in_sizes, int n_in,
                              void* d_out, int out_size)
{
    const float* x   = (const float*)d_in[0];
    const int*   ei  = (const int*)d_in[1];    // int64 tensors arrive as int32
    const int*   eli = (const int*)d_in[2];
    const float* W1  = (const float*)d_in[3];
    const float* b1  = (const float*)d_in[4];
    const float* W2  = (const float*)d_in[5];
    const float* b2  = (const float*)d_in[6];
    float* out = (float*)d_out;

    int n  = in_sizes[0] / DD;
    int E  = in_sizes[1] / 2;
    int el = in_sizes[2] / 2;

    __half* h = nullptr; float* z = nullptr;
    __nv_bfloat16 *w1hi = nullptr, *w1lo = nullptr, *w2hi = nullptr, *w2lo = nullptr;
    cudaGetSymbolAddress((void**)&h, g_h);
    cudaGetSymbolAddress((void**)&z, g_z);
    cudaGetSymbolAddress((void**)&w1hi, g_w1hi);
    cudaGetSymbolAddress((void**)&w1lo, g_w1lo);
    cudaGetSymbolAddress((void**)&w2hi, g_w2hi);
    cudaGetSymbolAddress((void**)&w2lo, g_w2lo);

    cudaFuncSetAttribute(gemm_mma_kernel, cudaFuncAttributeMaxDynamicSharedMemorySize, GSM_BYTES);

    const int T = 256;
    int nb_n = (n + T - 1) / T;
    int nb_e = (E + T - 1) / T;
    int nb_warpN = (n * 32 + T - 1) / T;
    int nb_warpL = (el * 32 + T - 1) / T;
    int nb_gemm = (n + 127) / 128;
    int nb_scan = (n + SCAN_BLK - 1) / SCAN_BLK;

    // graph preprocessing
    zero_count_kernel<<<nb_n, T>>>(n);
    count_kernel<<<nb_e, T>>>(ei, E, n);
    dinv_kernel<<<nb_n, T>>>(n);
    scan1_kernel<<<nb_scan, SCAN_BLK>>>(n);
    scan2_kernel<<<1, SCAN_BLK>>>(nb_scan);
    scan3_kernel<<<nb_scan, SCAN_BLK>>>(n, nb_scan);
    fill_kernel<<<nb_e, T>>>(ei, E, n);
    convert_w_kernel<<<(DD * DD + 255) / 256, 256>>>(W1, W2);

    // layer 1: h = fp16(x@W1) ; z = relu(agg(h) + b1)
    gemm_mma_kernel<<<nb_gemm, T, GSM_BYTES>>>(x, w1hi, w1lo, h, n);
    aggregate_kernel<<<nb_warpN, T>>>(h, b1, z, n);

    // layer 2: h = fp16(z@W2) ; z = relu(agg(h) + b2)
    gemm_mma_kernel<<<nb_gemm, T, GSM_BYTES>>>(z, w2hi, w2lo, h, n);
    aggregate_kernel<<<nb_warpN, T>>>(h, b2, z, n);

    // decode
    decode_kernel<<<nb_warpL, T>>>(z, eli, out, el);
}

// round 7
// speedup vs baseline: 1.7929x; 1.0379x over previous
#include <cuda_runtime.h>
#include <cuda_bf16.h>
#include <cuda_fp16.h>
#include <cstdint>

#define NN 100000
#define EE 1600000
#define DD 128
#define SCAN_BLK 1024
#define GPITCH 136   // bf16 elements per smem row (128 + 8 pad -> conflict-free ldmatrix)

// ---------------- scratch (static device arrays; no allocation) ----------------
__device__ __half g_h[(size_t)NN * DD];   // GEMM output (fp16), aggregation input
__device__ __half g_z[(size_t)NN * DD];   // aggregation output (fp16)
__device__ int   g_count[NN];
__device__ int   g_rowptr[NN + 1];
__device__ int   g_cursor[NN];
__device__ float g_dinv[NN];
__device__ int   g_csrc[EE];
__device__ float g_cw[EE];
__device__ int   g_blocksum[1024];
__device__ int   g_blockoff[1025];
// bf16 split of W1^T / W2^T : [n][k] layout (row = output col, k contiguous)
__device__ __nv_bfloat16 g_w1hi[DD * DD];
__device__ __nv_bfloat16 g_w1lo[DD * DD];
__device__ __nv_bfloat16 g_w2hi[DD * DD];
__device__ __nv_bfloat16 g_w2lo[DD * DD];

__device__ __forceinline__ uint32_t smem_u32(const void* p) {
    uint32_t a;
    asm("{ .reg .u64 t; cvta.to.shared.u64 t, %1; cvt.u32.u64 %0, t; }" : "=r"(a) : "l"(p));
    return a;
}

// ---------------- fused: zero counters + split W1/W2 to bf16 hi/lo ----------------
__global__ void zero_convert_kernel(const float* __restrict__ W1, const float* __restrict__ W2, int n) {
    int i = blockIdx.x * blockDim.x + threadIdx.x;
    if (i < n) g_count[i] = 0;
    if (i < DD * DD) {
        int nn = i >> 7, kk = i & 127;
        float w1 = W1[kk * DD + nn];
        __nv_bfloat16 h1 = __float2bfloat16(w1);
        g_w1hi[nn * DD + kk] = h1;
        g_w1lo[nn * DD + kk] = __float2bfloat16(w1 - __bfloat162float(h1));
        float w2 = W2[kk * DD + nn];
        __nv_bfloat16 h2 = __float2bfloat16(w2);
        g_w2hi[nn * DD + kk] = h2;
        g_w2lo[nn * DD + kk] = __float2bfloat16(w2 - __bfloat162float(h2));
    }
}

__global__ void count_kernel(const int* __restrict__ ei, int E, int n) {
    int e = blockIdx.x * blockDim.x + threadIdx.x;
    if (e < E) {
        int d = ei[(size_t)E + e];
        if ((unsigned)d < (unsigned)n) atomicAdd(&g_count[d], 1);
    }
}

__device__ __forceinline__ int block_scan_incl(int v, int* wsum) {
    int lane = threadIdx.x & 31, wid = threadIdx.x >> 5;
    int x = v;
    #pragma unroll
    for (int off = 1; off < 32; off <<= 1) {
        int y = __shfl_up_sync(0xFFFFFFFFu, x, off);
        if (lane >= off) x += y;
    }
    if (lane == 31) wsum[wid] = x;
    __syncthreads();
    if (wid == 0) {
        int s = wsum[lane];
        #pragma unroll
        for (int off = 1; off < 32; off <<= 1) {
            int y = __shfl_up_sync(0xFFFFFFFFu, s, off);
            if (lane >= off) s += y;
        }
        wsum[lane] = s;
    }
    __syncthreads();
    return x + (wid > 0 ? wsum[wid - 1] : 0);
}

// phase 1 (+ fused dinv): per-block exclusive scan, block totals
__global__ __launch_bounds__(SCAN_BLK) void scan1_kernel(int n) {
    __shared__ int wsum[32];
    int idx = blockIdx.x * SCAN_BLK + threadIdx.x;
    int v = (idx < n) ? g_count[idx] : 0;
    if (idx < n) g_dinv[idx] = rsqrtf((float)v + 1.0f);   // +1 self loop
    int incl = block_scan_incl(v, wsum);
    if (idx < n) g_rowptr[idx] = incl - v;
    if (threadIdx.x == SCAN_BLK - 1) g_blocksum[blockIdx.x] = incl;
}

__global__ __launch_bounds__(SCAN_BLK) void scan2_kernel(int nb) {
    __shared__ int wsum[32];
    int t = threadIdx.x;
    int v = (t < nb) ? g_blocksum[t] : 0;
    int incl = block_scan_incl(v, wsum);
    if (t < nb) g_blockoff[t] = incl - v;
    if (t == nb - 1) g_blockoff[nb] = incl;
}

__global__ __launch_bounds__(SCAN_BLK) void scan3_kernel(int n, int nb) {
    int idx = blockIdx.x * SCAN_BLK + threadIdx.x;
    if (idx < n) {
        int r = g_rowptr[idx] + g_blockoff[blockIdx.x];
        g_rowptr[idx] = r;
        g_cursor[idx] = r;
    }
    if (idx == 0) g_rowptr[n] = g_blockoff[nb];
}

__global__ void fill_kernel(const int* __restrict__ ei, int E, int n) {
    int e = blockIdx.x * blockDim.x + threadIdx.x;
    if (e < E) {
        int s = ei[e];
        int d = ei[(size_t)E + e];
        if ((unsigned)s < (unsigned)n && (unsigned)d < (unsigned)n) {
            int p = atomicAdd(&g_cursor[d], 1);
            g_csrc[p] = s;
            g_cw[p] = g_dinv[s] * g_dinv[d];
        }
    }
}

// ---------------- mma.sync helpers ----------------
__device__ __forceinline__ void ldsm_x4(uint32_t addr, uint32_t& r0, uint32_t& r1, uint32_t& r2, uint32_t& r3) {
    asm volatile("ldmatrix.sync.aligned.m8n8.x4.shared.b16 {%0,%1,%2,%3}, [%4];"
        : "=r"(r0), "=r"(r1), "=r"(r2), "=r"(r3) : "r"(addr));
}
__device__ __forceinline__ void mma_bf16(float* c, uint32_t a0, uint32_t a1, uint32_t a2, uint32_t a3,
                                         uint32_t b0, uint32_t b1) {
    asm volatile("mma.sync.aligned.m16n8k16.row.col.f32.bf16.bf16.f32 "
        "{%0,%1,%2,%3}, {%4,%5,%6,%7}, {%8,%9}, {%0,%1,%2,%3};"
        : "+f"(c[0]), "+f"(c[1]), "+f"(c[2]), "+f"(c[3])
        : "r"(a0), "r"(a1), "r"(a2), "r"(a3), "r"(b0), "r"(b1));
}

// input row loader: float4 worth of values from fp32 or fp16 source
__device__ __forceinline__ float4 load4(const float* p) { return *(const float4*)p; }
__device__ __forceinline__ float4 load4(const __half* p) {
    uint2 raw = *(const uint2*)p;
    __half2 p0 = *reinterpret_cast<__half2*>(&raw.x);
    __half2 p1 = *reinterpret_cast<__half2*>(&raw.y);
    float2 f0 = __half22float2(p0), f1 = __half22float2(p1);
    return make_float4(f0.x, f0.y, f1.x, f1.y);
}

// ---------------- GEMM via mma.sync: C[n x 128] = A[n x 128] @ W[128 x 128] -> fp16 ----------
// 3-term bf16 split: C = Ahi*Whi + Alo*Whi + Ahi*Wlo  (fp32 accumulate)
#define GSM_BYTES (4 * 128 * GPITCH * 2)

template <typename TIN>
__global__ __launch_bounds__(256) void gemm_mma_kernel(
    const TIN* __restrict__ A,
    const __nv_bfloat16* __restrict__ Wthi,
    const __nv_bfloat16* __restrict__ Wtlo,
    __half* __restrict__ C, int n)
{
    extern __shared__ __align__(16) __nv_bfloat16 sm[];
    __nv_bfloat16* Xhi = sm;                       // 128 x GPITCH
    __nv_bfloat16* Xlo = Xhi + 128 * GPITCH;
    __nv_bfloat16* Whi = Xlo + 128 * GPITCH;
    __nv_bfloat16* Wlo = Whi + 128 * GPITCH;

    int tid = threadIdx.x;
    int w = tid >> 5, l = tid & 31;
    int block_row = blockIdx.x * 128;

    // ---- load + split X tile (128 x 128 -> bf16 hi/lo) ----
    #pragma unroll
    for (int it = 0; it < 16; it++) {
        int idx = tid + it * 256;       // 4-elem group index 0..4095
        int r = idx >> 5;
        int c = (idx & 31) * 4;
        int grow = block_row + r;
        float4 v = make_float4(0.f, 0.f, 0.f, 0.f);
        if (grow < n) v = load4(A + (size_t)grow * 128 + c);
        __nv_bfloat16 h0 = __float2bfloat16(v.x), h1 = __float2bfloat16(v.y);
        __nv_bfloat16 h2 = __float2bfloat16(v.z), h3 = __float2bfloat16(v.w);
        *(__nv_bfloat162*)&Xhi[r * GPITCH + c]     = __nv_bfloat162(h0, h1);
        *(__nv_bfloat162*)&Xhi[r * GPITCH + c + 2] = __nv_bfloat162(h2, h3);
        *(__nv_bfloat162*)&Xlo[r * GPITCH + c] =
            __nv_bfloat162(__float2bfloat16(v.x - __bfloat162float(h0)),
                           __float2bfloat16(v.y - __bfloat162float(h1)));
        *(__nv_bfloat162*)&Xlo[r * GPITCH + c + 2] =
            __nv_bfloat162(__float2bfloat16(v.z - __bfloat162float(h2)),
                           __float2bfloat16(v.w - __bfloat162float(h3)));
    }
    // ---- load W hi/lo ([n][k] bf16, contiguous) ----
    #pragma unroll
    for (int it = 0; it < 32; it++) {
        int idx = tid + it * 256;       // u32 index 0..8191
        int r = idx >> 6;
        int c = (idx & 63) * 2;
        *(uint32_t*)&Whi[r * GPITCH + c] = *(const uint32_t*)(Wthi + (size_t)r * 128 + c);
        *(uint32_t*)&Wlo[r * GPITCH + c] = *(const uint32_t*)(Wtlo + (size_t)r * 128 + c);
    }
    __syncthreads();

    uint32_t sbase = smem_u32(sm);
    uint32_t a_off = (uint32_t)(((w * 16 + (l & 15)) * GPITCH + (l >> 4) * 8) * 2);
    uint32_t ahi_addr = sbase + a_off;
    uint32_t alo_addr = sbase + (uint32_t)(128 * GPITCH * 2) + a_off;
    uint32_t b_off = (uint32_t)((((l & 7) + ((l >> 4) << 3)) * GPITCH + ((l >> 3) & 1) * 8) * 2);
    uint32_t bhi_addr = sbase + (uint32_t)(2 * 128 * GPITCH * 2) + b_off;
    uint32_t blo_addr = sbase + (uint32_t)(3 * 128 * GPITCH * 2) + b_off;

    float acc[16][4];
    #pragma unroll
    for (int j = 0; j < 16; j++)
        #pragma unroll
        for (int q = 0; q < 4; q++) acc[j][q] = 0.0f;

    #pragma unroll
    for (int kk = 0; kk < 8; kk++) {
        uint32_t ka = kk * 32;   // 16 bf16 = 32 bytes
        uint32_t ah0, ah1, ah2, ah3, al0, al1, al2, al3;
        ldsm_x4(ahi_addr + ka, ah0, ah1, ah2, ah3);
        ldsm_x4(alo_addr + ka, al0, al1, al2, al3);
        #pragma unroll
        for (int j2 = 0; j2 < 8; j2++) {
            uint32_t boff = (uint32_t)(j2 * 16 * GPITCH * 2) + ka;
            uint32_t bh0, bh1, bh2, bh3, bl0, bl1, bl2, bl3;
            ldsm_x4(bhi_addr + boff, bh0, bh1, bh2, bh3);
            ldsm_x4(blo_addr + boff, bl0, bl1, bl2, bl3);
            mma_bf16(acc[2 * j2],     ah0, ah1, ah2, ah3, bh0, bh1);
            mma_bf16(acc[2 * j2],     al0, al1, al2, al3, bh0, bh1);
            mma_bf16(acc[2 * j2],     ah0, ah1, ah2, ah3, bl0, bl1);
            mma_bf16(acc[2 * j2 + 1], ah0, ah1, ah2, ah3, bh2, bh3);
            mma_bf16(acc[2 * j2 + 1], al0, al1, al2, al3, bh2, bh3);
            mma_bf16(acc[2 * j2 + 1], ah0, ah1, ah2, ah3, bl2, bl3);
        }
    }

    // ---- epilogue: fragment -> global fp16 ----
    int g = l >> 2, t = l & 3;
    int row0 = block_row + w * 16 + g;
    int row1 = row0 + 8;
    #pragma unroll
    for (int j = 0; j < 16; j++) {
        int col = j * 8 + t * 2;
        if (row0 < n) *(__half2*)(C + (size_t)row0 * 128 + col) = __floats2half2_rn(acc[j][0], acc[j][1]);
        if (row1 < n) *(__half2*)(C + (size_t)row1 * 128 + col) = __floats2half2_rn(acc[j][2], acc[j][3]);
    }
}

// ---------------- aggregation: z16[i] = relu(sum h16[src]*w + h16[i]*dinv^2 + b) ----------------
__device__ __forceinline__ float4 half4_to_float4(uint2 raw) {
    __half2 p0 = *reinterpret_cast<__half2*>(&raw.x);
    __half2 p1 = *reinterpret_cast<__half2*>(&raw.y);
    float2 f0 = __half22float2(p0), f1 = __half22float2(p1);
    return make_float4(f0.x, f0.y, f1.x, f1.y);
}

__global__ __launch_bounds__(256) void aggregate_kernel(
    const __half* __restrict__ h, const float* __restrict__ bias,
    __half* __restrict__ out, int n)
{
    int warp = (blockIdx.x * blockDim.x + threadIdx.x) >> 5;
    int lane = threadIdx.x & 31;
    if (warp >= n) return;
    int i = warp;

    float di = g_dinv[i];
    float w0 = di * di;
    float4 v = half4_to_float4(((const uint2*)(h + (size_t)i * 128))[lane]);
    float4 acc  = make_float4(v.x * w0, v.y * w0, v.z * w0, v.w * w0);
    float4 acc2 = make_float4(0.f, 0.f, 0.f, 0.f);

    int e0 = g_rowptr[i], e1 = g_rowptr[i + 1];
    int e = e0;
    for (; e + 3 < e1; e += 4) {
        int s0 = g_csrc[e];     float w_0 = g_cw[e];
        int s1 = g_csrc[e + 1]; float w_1 = g_cw[e + 1];
        int s2 = g_csrc[e + 2]; float w_2 = g_cw[e + 2];
        int s3 = g_csrc[e + 3]; float w_3 = g_cw[e + 3];
        uint2 r0 = ((const uint2*)(h + (size_t)s0 * 128))[lane];
        uint2 r1 = ((const uint2*)(h + (size_t)s1 * 128))[lane];
        uint2 r2 = ((const uint2*)(h + (size_t)s2 * 128))[lane];
        uint2 r3 = ((const uint2*)(h + (size_t)s3 * 128))[lane];
        float4 h0 = half4_to_float4(r0), h1 = half4_to_float4(r1);
        float4 h2 = half4_to_float4(r2), h3 = half4_to_float4(r3);
        acc.x  = fmaf(h0.x, w_0, acc.x);  acc.y  = fmaf(h0.y, w_0, acc.y);
        acc.z  = fmaf(h0.z, w_0, acc.z);  acc.w  = fmaf(h0.w, w_0, acc.w);
        acc2.x = fmaf(h1.x, w_1, acc2.x); acc2.y = fmaf(h1.y, w_1, acc2.y);
        acc2.z = fmaf(h1.z, w_1, acc2.z); acc2.w = fmaf(h1.w, w_1, acc2.w);
        acc.x  = fmaf(h2.x, w_2, acc.x);  acc.y  = fmaf(h2.y, w_2, acc.y);
        acc.z  = fmaf(h2.z, w_2, acc.z);  acc.w  = fmaf(h2.w, w_2, acc.w);
        acc2.x = fmaf(h3.x, w_3, acc2.x); acc2.y = fmaf(h3.y, w_3, acc2.y);
        acc2.z = fmaf(h3.z, w_3, acc2.z); acc2.w = fmaf(h3.w, w_3, acc2.w);
    }
    for (; e < e1; e++) {
        int s0 = g_csrc[e]; float w_0 = g_cw[e];
        float4 h0 = half4_to_float4(((const uint2*)(h + (size_t)s0 * 128))[lane]);
        acc.x = fmaf(h0.x, w_0, acc.x); acc.y = fmaf(h0.y, w_0, acc.y);
        acc.z = fmaf(h0.z, w_0, acc.z); acc.w = fmaf(h0.w, w_0, acc.w);
    }
    acc.x += acc2.x; acc.y += acc2.y; acc.z += acc2.z; acc.w += acc2.w;

    float4 bb = ((const float4*)bias)[lane];
    acc.x = fmaxf(acc.x + bb.x, 0.0f);
    acc.y = fmaxf(acc.y + bb.y, 0.0f);
    acc.z = fmaxf(acc.z + bb.z, 0.0f);
    acc.w = fmaxf(acc.w + bb.w, 0.0f);
    uint2 packed;
    *reinterpret_cast<__half2*>(&packed.x) = __floats2half2_rn(acc.x, acc.y);
    *reinterpret_cast<__half2*>(&packed.y) = __floats2half2_rn(acc.z, acc.w);
    ((uint2*)(out + (size_t)i * 128))[lane] = packed;
}

// ---------------- decode: out[e] = dot(z16[s], z16[d]) ----------------
__global__ __launch_bounds__(256) void decode_kernel(
    const __half* __restrict__ z, const int* __restrict__ eli,
    float* __restrict__ out, int el)
{
    int warp = (blockIdx.x * blockDim.x + threadIdx.x) >> 5;
    int lane = threadIdx.x & 31;
    if (warp >= el) return;
    int s = eli[warp];
    int d = eli[(size_t)el + warp];
    float4 a = half4_to_float4(((const uint2*)(z + (size_t)s * 128))[lane]);
    float4 b = half4_to_float4(((const uint2*)(z + (size_t)d * 128))[lane]);
    float p = a.x * b.x + a.y * b.y + a.z * b.z + a.w * b.w;
    #pragma unroll
    for (int off = 16; off; off >>= 1) p += __shfl_down_sync(0xFFFFFFFFu, p, off);
    if (lane == 0) out[warp] = p;
}

// ---------------- launch ----------------
extern "C" void kernel_launch(void* const* d_in, const int* in_sizes, int n_in,
                              void* d_out, int out_size)
{
    const float* x   = (const float*)d_in[0];
    const int*   ei  = (const int*)d_in[1];    // int64 tensors arrive as int32
    const int*   eli = (const int*)d_in[2];
    const float* W1  = (const float*)d_in[3];
    const float* b1  = (const float*)d_in[4];
    const float* W2  = (const float*)d_in[5];
    const float* b2  = (const float*)d_in[6];
    float* out = (float*)d_out;

    int n  = in_sizes[0] / DD;
    int E  = in_sizes[1] / 2;
    int el = in_sizes[2] / 2;

    __half* h = nullptr; __half* z = nullptr;
    __nv_bfloat16 *w1hi = nullptr, *w1lo = nullptr, *w2hi = nullptr, *w2lo = nullptr;
    cudaGetSymbolAddress((void**)&h, g_h);
    cudaGetSymbolAddress((void**)&z, g_z);
    cudaGetSymbolAddress((void**)&w1hi, g_w1hi);
    cudaGetSymbolAddress((void**)&w1lo, g_w1lo);
    cudaGetSymbolAddress((void**)&w2hi, g_w2hi);
    cudaGetSymbolAddress((void**)&w2lo, g_w2lo);

    cudaFuncSetAttribute(gemm_mma_kernel<float>,  cudaFuncAttributeMaxDynamicSharedMemorySize, GSM_BYTES);
    cudaFuncSetAttribute(gemm_mma_kernel<__half>, cudaFuncAttributeMaxDynamicSharedMemorySize, GSM_BYTES);

    const int T = 256;
    int nz = (n > DD * DD) ? n : DD * DD;
    int nb_z = (nz + T - 1) / T;
    int nb_e = (E + T - 1) / T;
    int nb_warpN = (n * 32 + T - 1) / T;
    int nb_warpL = (el * 32 + T - 1) / T;
    int nb_gemm = (n + 127) / 128;
    int nb_scan = (n + SCAN_BLK - 1) / SCAN_BLK;

    // graph preprocessing (+ weight conversion fused into first launch)
    zero_convert_kernel<<<nb_z, T>>>(W1, W2, n);
    count_kernel<<<nb_e, T>>>(ei, E, n);
    scan1_kernel<<<nb_scan, SCAN_BLK>>>(n);     // also computes dinv
    scan2_kernel<<<1, SCAN_BLK>>>(nb_scan);
    scan3_kernel<<<nb_scan, SCAN_BLK>>>(n, nb_scan);
    fill_kernel<<<nb_e, T>>>(ei, E, n);

    // layer 1: h = fp16(x@W1) ; z = fp16(relu(agg(h) + b1))
    gemm_mma_kernel<float><<<nb_gemm, T, GSM_BYTES>>>(x, w1hi, w1lo, h, n);
    aggregate_kernel<<<nb_warpN, T>>>(h, b1, z, n);

    // layer 2: h = fp16(z@W2) ; z = fp16(relu(agg(h) + b2))
    gemm_mma_kernel<__half><<<nb_gemm, T, GSM_BYTES>>>(z, w2hi, w2lo, h, n);
    aggregate_kernel<<<nb_warpN, T>>>(h, b2, z, n);

    // decode
    decode_kernel<<<nb_warpL, T>>>(z, eli, out, el);
}

// round 8
// speedup vs baseline: 1.8582x; 1.0364x over previous
#include <cuda_runtime.h>
#include <cuda_bf16.h>
#include <cuda_fp16.h>
#include <cstdint>

#define NN 100000
#define EE 1600000
#define DD 128
#define SCAN_BLK 1024
#define GPITCH 136   // bf16 elements per smem row (128 + 8 pad -> conflict-free ldmatrix)

// ---------------- scratch (static device arrays; no allocation) ----------------
__device__ __half g_h[(size_t)NN * DD];   // GEMM output (fp16), aggregation input
__device__ __half g_z[(size_t)NN * DD];   // aggregation output (fp16)
__device__ int   g_count[NN];
__device__ int   g_rowptr[NN + 1];
__device__ int   g_cursor[NN];
__device__ float g_dinv[NN];
__device__ int   g_csrc[EE];
__device__ float g_cw[EE];
__device__ int   g_blocksum[1024];
__device__ int   g_blockoff[1025];
// bf16 split of W1^T / W2^T : [n][k] layout (row = output col, k contiguous)
__device__ __nv_bfloat16 g_w1hi[DD * DD];
__device__ __nv_bfloat16 g_w1lo[DD * DD];
__device__ __nv_bfloat16 g_w2hi[DD * DD];
__device__ __nv_bfloat16 g_w2lo[DD * DD];

__device__ __forceinline__ uint32_t smem_u32(const void* p) {
    uint32_t a;
    asm("{ .reg .u64 t; cvta.to.shared.u64 t, %1; cvt.u32.u64 %0, t; }" : "=r"(a) : "l"(p));
    return a;
}

// ---------------- preprocessing kernels ----------------
__global__ void zero_count_kernel(int n) {
    int i = blockIdx.x * blockDim.x + threadIdx.x;
    if (i < n) g_count[i] = 0;
}

// split W1/W2 to bf16 hi/lo (runs on side stream, feeds gemm1 only... gemm2 too)
__global__ void convert_w_kernel(const float* __restrict__ W1, const float* __restrict__ W2) {
    int i = blockIdx.x * blockDim.x + threadIdx.x;
    if (i >= DD * DD) return;
    int nn = i >> 7, kk = i & 127;
    float w1 = W1[kk * DD + nn];
    __nv_bfloat16 h1 = __float2bfloat16(w1);
    g_w1hi[nn * DD + kk] = h1;
    g_w1lo[nn * DD + kk] = __float2bfloat16(w1 - __bfloat162float(h1));
    float w2 = W2[kk * DD + nn];
    __nv_bfloat16 h2 = __float2bfloat16(w2);
    g_w2hi[nn * DD + kk] = h2;
    g_w2lo[nn * DD + kk] = __float2bfloat16(w2 - __bfloat162float(h2));
}

__global__ void count_kernel(const int* __restrict__ ei, int E, int n) {
    int e = blockIdx.x * blockDim.x + threadIdx.x;
    if (e < E) {
        int d = ei[(size_t)E + e];
        if ((unsigned)d < (unsigned)n) atomicAdd(&g_count[d], 1);
    }
}

__device__ __forceinline__ int block_scan_incl(int v, int* wsum) {
    int lane = threadIdx.x & 31, wid = threadIdx.x >> 5;
    int x = v;
    #pragma unroll
    for (int off = 1; off < 32; off <<= 1) {
        int y = __shfl_up_sync(0xFFFFFFFFu, x, off);
        if (lane >= off) x += y;
    }
    if (lane == 31) wsum[wid] = x;
    __syncthreads();
    if (wid == 0) {
        int s = wsum[lane];
        #pragma unroll
        for (int off = 1; off < 32; off <<= 1) {
            int y = __shfl_up_sync(0xFFFFFFFFu, s, off);
            if (lane >= off) s += y;
        }
        wsum[lane] = s;
    }
    __syncthreads();
    return x + (wid > 0 ? wsum[wid - 1] : 0);
}

// phase 1 (+ fused dinv)
__global__ __launch_bounds__(SCAN_BLK) void scan1_kernel(int n) {
    __shared__ int wsum[32];
    int idx = blockIdx.x * SCAN_BLK + threadIdx.x;
    int v = (idx < n) ? g_count[idx] : 0;
    if (idx < n) g_dinv[idx] = rsqrtf((float)v + 1.0f);   // +1 self loop
    int incl = block_scan_incl(v, wsum);
    if (idx < n) g_rowptr[idx] = incl - v;
    if (threadIdx.x == SCAN_BLK - 1) g_blocksum[blockIdx.x] = incl;
}

__global__ __launch_bounds__(SCAN_BLK) void scan2_kernel(int nb) {
    __shared__ int wsum[32];
    int t = threadIdx.x;
    int v = (t < nb) ? g_blocksum[t] : 0;
    int incl = block_scan_incl(v, wsum);
    if (t < nb) g_blockoff[t] = incl - v;
    if (t == nb - 1) g_blockoff[nb] = incl;
}

__global__ __launch_bounds__(SCAN_BLK) void scan3_kernel(int n, int nb) {
    int idx = blockIdx.x * SCAN_BLK + threadIdx.x;
    if (idx < n) {
        int r = g_rowptr[idx] + g_blockoff[blockIdx.x];
        g_rowptr[idx] = r;
        g_cursor[idx] = r;
    }
    if (idx == 0) g_rowptr[n] = g_blockoff[nb];
}

__global__ void fill_kernel(const int* __restrict__ ei, int E, int n) {
    int e = blockIdx.x * blockDim.x + threadIdx.x;
    if (e < E) {
        int s = ei[e];
        int d = ei[(size_t)E + e];
        if ((unsigned)s < (unsigned)n && (unsigned)d < (unsigned)n) {
            int p = atomicAdd(&g_cursor[d], 1);
            g_csrc[p] = s;
            g_cw[p] = g_dinv[s] * g_dinv[d];
        }
    }
}

// ---------------- mma.sync helpers ----------------
__device__ __forceinline__ void ldsm_x4(uint32_t addr, uint32_t& r0, uint32_t& r1, uint32_t& r2, uint32_t& r3) {
    asm volatile("ldmatrix.sync.aligned.m8n8.x4.shared.b16 {%0,%1,%2,%3}, [%4];"
        : "=r"(r0), "=r"(r1), "=r"(r2), "=r"(r3) : "r"(addr));
}
__device__ __forceinline__ void mma_bf16(float* c, uint32_t a0, uint32_t a1, uint32_t a2, uint32_t a3,
                                         uint32_t b0, uint32_t b1) {
    asm volatile("mma.sync.aligned.m16n8k16.row.col.f32.bf16.bf16.f32 "
        "{%0,%1,%2,%3}, {%4,%5,%6,%7}, {%8,%9}, {%0,%1,%2,%3};"
        : "+f"(c[0]), "+f"(c[1]), "+f"(c[2]), "+f"(c[3])
        : "r"(a0), "r"(a1), "r"(a2), "r"(a3), "r"(b0), "r"(b1));
}

__device__ __forceinline__ float4 load4(const float* p) { return *(const float4*)p; }
__device__ __forceinline__ float4 load4(const __half* p) {
    uint2 raw = *(const uint2*)p;
    __half2 p0 = *reinterpret_cast<__half2*>(&raw.x);
    __half2 p1 = *reinterpret_cast<__half2*>(&raw.y);
    float2 f0 = __half22float2(p0), f1 = __half22float2(p1);
    return make_float4(f0.x, f0.y, f1.x, f1.y);
}

// ---------------- GEMM via mma.sync -> fp16 out (3-term bf16 split, fp32 accum) ----------
#define GSM_BYTES (4 * 128 * GPITCH * 2)

template <typename TIN>
__global__ __launch_bounds__(256) void gemm_mma_kernel(
    const TIN* __restrict__ A,
    const __nv_bfloat16* __restrict__ Wthi,
    const __nv_bfloat16* __restrict__ Wtlo,
    __half* __restrict__ C, int n)
{
    extern __shared__ __align__(16) __nv_bfloat16 sm[];
    __nv_bfloat16* Xhi = sm;
    __nv_bfloat16* Xlo = Xhi + 128 * GPITCH;
    __nv_bfloat16* Whi = Xlo + 128 * GPITCH;
    __nv_bfloat16* Wlo = Whi + 128 * GPITCH;

    int tid = threadIdx.x;
    int w = tid >> 5, l = tid & 31;
    int block_row = blockIdx.x * 128;

    #pragma unroll
    for (int it = 0; it < 16; it++) {
        int idx = tid + it * 256;
        int r = idx >> 5;
        int c = (idx & 31) * 4;
        int grow = block_row + r;
        float4 v = make_float4(0.f, 0.f, 0.f, 0.f);
        if (grow < n) v = load4(A + (size_t)grow * 128 + c);
        __nv_bfloat16 h0 = __float2bfloat16(v.x), h1 = __float2bfloat16(v.y);
        __nv_bfloat16 h2 = __float2bfloat16(v.z), h3 = __float2bfloat16(v.w);
        *(__nv_bfloat162*)&Xhi[r * GPITCH + c]     = __nv_bfloat162(h0, h1);
        *(__nv_bfloat162*)&Xhi[r * GPITCH + c + 2] = __nv_bfloat162(h2, h3);
        *(__nv_bfloat162*)&Xlo[r * GPITCH + c] =
            __nv_bfloat162(__float2bfloat16(v.x - __bfloat162float(h0)),
                           __float2bfloat16(v.y - __bfloat162float(h1)));
        *(__nv_bfloat162*)&Xlo[r * GPITCH + c + 2] =
            __nv_bfloat162(__float2bfloat16(v.z - __bfloat162float(h2)),
                           __float2bfloat16(v.w - __bfloat162float(h3)));
    }
    #pragma unroll
    for (int it = 0; it < 32; it++) {
        int idx = tid + it * 256;
        int r = idx >> 6;
        int c = (idx & 63) * 2;
        *(uint32_t*)&Whi[r * GPITCH + c] = *(const uint32_t*)(Wthi + (size_t)r * 128 + c);
        *(uint32_t*)&Wlo[r * GPITCH + c] = *(const uint32_t*)(Wtlo + (size_t)r * 128 + c);
    }
    __syncthreads();

    uint32_t sbase = smem_u32(sm);
    uint32_t a_off = (uint32_t)(((w * 16 + (l & 15)) * GPITCH + (l >> 4) * 8) * 2);
    uint32_t ahi_addr = sbase + a_off;
    uint32_t alo_addr = sbase + (uint32_t)(128 * GPITCH * 2) + a_off;
    uint32_t b_off = (uint32_t)((((l & 7) + ((l >> 4) << 3)) * GPITCH + ((l >> 3) & 1) * 8) * 2);
    uint32_t bhi_addr = sbase + (uint32_t)(2 * 128 * GPITCH * 2) + b_off;
    uint32_t blo_addr = sbase + (uint32_t)(3 * 128 * GPITCH * 2) + b_off;

    float acc[16][4];
    #pragma unroll
    for (int j = 0; j < 16; j++)
        #pragma unroll
        for (int q = 0; q < 4; q++) acc[j][q] = 0.0f;

    #pragma unroll
    for (int kk = 0; kk < 8; kk++) {
        uint32_t ka = kk * 32;
        uint32_t ah0, ah1, ah2, ah3, al0, al1, al2, al3;
        ldsm_x4(ahi_addr + ka, ah0, ah1, ah2, ah3);
        ldsm_x4(alo_addr + ka, al0, al1, al2, al3);
        #pragma unroll
        for (int j2 = 0; j2 < 8; j2++) {
            uint32_t boff = (uint32_t)(j2 * 16 * GPITCH * 2) + ka;
            uint32_t bh0, bh1, bh2, bh3, bl0, bl1, bl2, bl3;
            ldsm_x4(bhi_addr + boff, bh0, bh1, bh2, bh3);
            ldsm_x4(blo_addr + boff, bl0, bl1, bl2, bl3);
            mma_bf16(acc[2 * j2],     ah0, ah1, ah2, ah3, bh0, bh1);
            mma_bf16(acc[2 * j2],     al0, al1, al2, al3, bh0, bh1);
            mma_bf16(acc[2 * j2],     ah0, ah1, ah2, ah3, bl0, bl1);
            mma_bf16(acc[2 * j2 + 1], ah0, ah1, ah2, ah3, bh2, bh3);
            mma_bf16(acc[2 * j2 + 1], al0, al1, al2, al3, bh2, bh3);
            mma_bf16(acc[2 * j2 + 1], ah0, ah1, ah2, ah3, bl2, bl3);
        }
    }

    int g = l >> 2, t = l & 3;
    int row0 = block_row + w * 16 + g;
    int row1 = row0 + 8;
    #pragma unroll
    for (int j = 0; j < 16; j++) {
        int col = j * 8 + t * 2;
        if (row0 < n) *(__half2*)(C + (size_t)row0 * 128 + col) = __floats2half2_rn(acc[j][0], acc[j][1]);
        if (row1 < n) *(__half2*)(C + (size_t)row1 * 128 + col) = __floats2half2_rn(acc[j][2], acc[j][3]);
    }
}

// ---------------- aggregation ----------------
__device__ __forceinline__ float4 half4_to_float4(uint2 raw) {
    __half2 p0 = *reinterpret_cast<__half2*>(&raw.x);
    __half2 p1 = *reinterpret_cast<__half2*>(&raw.y);
    float2 f0 = __half22float2(p0), f1 = __half22float2(p1);
    return make_float4(f0.x, f0.y, f1.x, f1.y);
}

__global__ __launch_bounds__(256) void aggregate_kernel(
    const __half* __restrict__ h, const float* __restrict__ bias,
    __half* __restrict__ out, int n)
{
    int warp = (blockIdx.x * blockDim.x + threadIdx.x) >> 5;
    int lane = threadIdx.x & 31;
    if (warp >= n) return;
    int i = warp;

    float di = g_dinv[i];
    float w0 = di * di;
    float4 v = half4_to_float4(((const uint2*)(h + (size_t)i * 128))[lane]);
    float4 acc  = make_float4(v.x * w0, v.y * w0, v.z * w0, v.w * w0);
    float4 acc2 = make_float4(0.f, 0.f, 0.f, 0.f);

    int e0 = g_rowptr[i], e1 = g_rowptr[i + 1];
    int e = e0;
    for (; e + 3 < e1; e += 4) {
        int s0 = g_csrc[e];     float w_0 = g_cw[e];
        int s1 = g_csrc[e + 1]; float w_1 = g_cw[e + 1];
        int s2 = g_csrc[e + 2]; float w_2 = g_cw[e + 2];
        int s3 = g_csrc[e + 3]; float w_3 = g_cw[e + 3];
        uint2 r0 = ((const uint2*)(h + (size_t)s0 * 128))[lane];
        uint2 r1 = ((const uint2*)(h + (size_t)s1 * 128))[lane];
        uint2 r2 = ((const uint2*)(h + (size_t)s2 * 128))[lane];
        uint2 r3 = ((const uint2*)(h + (size_t)s3 * 128))[lane];
        float4 h0 = half4_to_float4(r0), h1 = half4_to_float4(r1);
        float4 h2 = half4_to_float4(r2), h3 = half4_to_float4(r3);
        acc.x  = fmaf(h0.x, w_0, acc.x);  acc.y  = fmaf(h0.y, w_0, acc.y);
        acc.z  = fmaf(h0.z, w_0, acc.z);  acc.w  = fmaf(h0.w, w_0, acc.w);
        acc2.x = fmaf(h1.x, w_1, acc2.x); acc2.y = fmaf(h1.y, w_1, acc2.y);
        acc2.z = fmaf(h1.z, w_1, acc2.z); acc2.w = fmaf(h1.w, w_1, acc2.w);
        acc.x  = fmaf(h2.x, w_2, acc.x);  acc.y  = fmaf(h2.y, w_2, acc.y);
        acc.z  = fmaf(h2.z, w_2, acc.z);  acc.w  = fmaf(h2.w, w_2, acc.w);
        acc2.x = fmaf(h3.x, w_3, acc2.x); acc2.y = fmaf(h3.y, w_3, acc2.y);
        acc2.z = fmaf(h3.z, w_3, acc2.z); acc2.w = fmaf(h3.w, w_3, acc2.w);
    }
    for (; e < e1; e++) {
        int s0 = g_csrc[e]; float w_0 = g_cw[e];
        float4 h0 = half4_to_float4(((const uint2*)(h + (size_t)s0 * 128))[lane]);
        acc.x = fmaf(h0.x, w_0, acc.x); acc.y = fmaf(h0.y, w_0, acc.y);
        acc.z = fmaf(h0.z, w_0, acc.z); acc.w = fmaf(h0.w, w_0, acc.w);
    }
    acc.x += acc2.x; acc.y += acc2.y; acc.z += acc2.z; acc.w += acc2.w;

    float4 bb = ((const float4*)bias)[lane];
    acc.x = fmaxf(acc.x + bb.x, 0.0f);
    acc.y = fmaxf(acc.y + bb.y, 0.0f);
    acc.z = fmaxf(acc.z + bb.z, 0.0f);
    acc.w = fmaxf(acc.w + bb.w, 0.0f);
    uint2 packed;
    *reinterpret_cast<__half2*>(&packed.x) = __floats2half2_rn(acc.x, acc.y);
    *reinterpret_cast<__half2*>(&packed.y) = __floats2half2_rn(acc.z, acc.w);
    ((uint2*)(out + (size_t)i * 128))[lane] = packed;
}

// ---------------- decode ----------------
__global__ __launch_bounds__(256) void decode_kernel(
    const __half* __restrict__ z, const int* __restrict__ eli,
    float* __restrict__ out, int el)
{
    int warp = (blockIdx.x * blockDim.x + threadIdx.x) >> 5;
    int lane = threadIdx.x & 31;
    if (warp >= el) return;
    int s = eli[warp];
    int d = eli[(size_t)el + warp];
    float4 a = half4_to_float4(((const uint2*)(z + (size_t)s * 128))[lane]);
    float4 b = half4_to_float4(((const uint2*)(z + (size_t)d * 128))[lane]);
    float p = a.x * b.x + a.y * b.y + a.z * b.z + a.w * b.w;
    #pragma unroll
    for (int off = 16; off; off >>= 1) p += __shfl_down_sync(0xFFFFFFFFu, p, off);
    if (lane == 0) out[warp] = p;
}

// ---------------- launch ----------------
extern "C" void kernel_launch(void* const* d_in, const int* in_sizes, int n_in,
                              void* d_out, int out_size)
{
    const float* x   = (const float*)d_in[0];
    const int*   ei  = (const int*)d_in[1];    // int64 tensors arrive as int32
    const int*   eli = (const int*)d_in[2];
    const float* W1  = (const float*)d_in[3];
    const float* b1  = (const float*)d_in[4];
    const float* W2  = (const float*)d_in[5];
    const float* b2  = (const float*)d_in[6];
    float* out = (float*)d_out;

    int n  = in_sizes[0] / DD;
    int E  = in_sizes[1] / 2;
    int el = in_sizes[2] / 2;

    __half* h = nullptr; __half* z = nullptr;
    __nv_bfloat16 *w1hi = nullptr, *w1lo = nullptr, *w2hi = nullptr, *w2lo = nullptr;
    cudaGetSymbolAddress((void**)&h, g_h);
    cudaGetSymbolAddress((void**)&z, g_z);
    cudaGetSymbolAddress((void**)&w1hi, g_w1hi);
    cudaGetSymbolAddress((void**)&w1lo, g_w1lo);
    cudaGetSymbolAddress((void**)&w2hi, g_w2hi);
    cudaGetSymbolAddress((void**)&w2lo, g_w2lo);

    cudaFuncSetAttribute(gemm_mma_kernel<float>,  cudaFuncAttributeMaxDynamicSharedMemorySize, GSM_BYTES);
    cudaFuncSetAttribute(gemm_mma_kernel<__half>, cudaFuncAttributeMaxDynamicSharedMemorySize, GSM_BYTES);

    const int T = 256;
    int nb_n = (n + T - 1) / T;
    int nb_e = (E + T - 1) / T;
    int nb_warpN = (n * 32 + T - 1) / T;
    int nb_warpL = (el * 32 + T - 1) / T;
    int nb_gemm = (n + 127) / 128;
    int nb_scan = (n + SCAN_BLK - 1) / SCAN_BLK;

    // fork a side stream: convert_w + gemm1 run concurrently with the prep chain
    cudaStream_t s2;
    cudaEvent_t evFork, evJoin;
    cudaStreamCreateWithFlags(&s2, cudaStreamNonBlocking);
    cudaEventCreateWithFlags(&evFork, cudaEventDisableTiming);
    cudaEventCreateWithFlags(&evJoin, cudaEventDisableTiming);

    cudaEventRecord(evFork, 0);
    cudaStreamWaitEvent(s2, evFork, 0);

    // side stream: weight split + layer-1 GEMM (depends only on x, W1, W2)
    convert_w_kernel<<<(DD * DD + T - 1) / T, T, 0, s2>>>(W1, W2);
    gemm_mma_kernel<float><<<nb_gemm, T, GSM_BYTES, s2>>>(x, w1hi, w1lo, h, n);
    cudaEventRecord(evJoin, s2);

    // default stream: graph preprocessing (depends only on edge_index)
    zero_count_kernel<<<nb_n, T>>>(n);
    count_kernel<<<nb_e, T>>>(ei, E, n);
    scan1_kernel<<<nb_scan, SCAN_BLK>>>(n);     // also computes dinv
    scan2_kernel<<<1, SCAN_BLK>>>(nb_scan);
    scan3_kernel<<<nb_scan, SCAN_BLK>>>(n, nb_scan);
    fill_kernel<<<nb_e, T>>>(ei, E, n);

    // join: aggregation needs both fill (CSC) and gemm1 (h)
    cudaStreamWaitEvent(0, evJoin, 0);
    aggregate_kernel<<<nb_warpN, T>>>(h, b1, z, n);

    // layer 2
    gemm_mma_kernel<__half><<<nb_gemm, T, GSM_BYTES>>>(z, w2hi, w2lo, h, n);
    aggregate_kernel<<<nb_warpN, T>>>(h, b2, z, n);

    // decode
    decode_kernel<<<nb_warpL, T>>>(z, eli, out, el);
}